// round 11
// baseline (speedup 1.0000x reference)
#include <cuda_runtime.h>
#include <cstdint>

#define NB   4
#define CIN  256
#define NSP  2304      // 48*48 tokens
#define NH   8
#define HDIM 64
#define HB   32        // NH*NB
// q pre-scale folds softmax scale AND log2(e): exp(s) == exp2(s')
#define QK_SCALE_L2E (0.125f * 1.44269504088896f)

typedef unsigned long long u64;

// Scratch (device globals — no allocations allowed)
// g_q: [hb][n][d], tf32-rounded, pre-scaled by 0.125*log2e
// g_k: [hb][n][perm(d)], tf32-rounded, cols permuted [0,4,1,5,2,6,3,7] per 8-group
// g_v: [hb][d][perm(n)], tf32-rounded, TRANSPOSED, n permuted per 8-group
__device__ float g_q  [(size_t)HB * NSP * HDIM];
__device__ float g_k  [(size_t)HB * NSP * HDIM];
__device__ float g_v  [(size_t)HB * NSP * HDIM];
__device__ float g_wsr[(size_t)4 * 512 * NSP];   // scrambled ws: [b2][c][p]

// ---- helpers ---------------------------------------------------------------
__device__ __forceinline__ uint32_t f2tf(float f) {
    uint32_t r;
    asm("cvt.rna.tf32.f32 %0, %1;" : "=r"(r) : "f"(f));
    return r;
}
__device__ __forceinline__ float tfv(float f) { return __uint_as_float(f2tf(f)); }
__device__ __forceinline__ void mma8(float* d, const uint32_t* a,
                                     uint32_t b0, uint32_t b1) {
    asm volatile(
        "mma.sync.aligned.m16n8k8.row.col.f32.tf32.tf32.f32 "
        "{%0,%1,%2,%3}, {%4,%5,%6,%7}, {%8,%9}, {%0,%1,%2,%3};"
        : "+f"(d[0]), "+f"(d[1]), "+f"(d[2]), "+f"(d[3])
        : "r"(a[0]), "r"(a[1]), "r"(a[2]), "r"(a[3]), "r"(b0), "r"(b1));
}
__device__ __forceinline__ uint32_t s2u(const void* p) {
    return (uint32_t)__cvta_generic_to_shared(p);
}
__device__ __forceinline__ void cp16(uint32_t smem_dst, const void* gsrc) {
    asm volatile("cp.async.cg.shared.global [%0], [%1], 16;"
                 :: "r"(smem_dst), "l"(gsrc));
}
// interleave permutation within 8-groups: [0,4,1,5,2,6,3,7]
__device__ __forceinline__ int perm8(int i) {
    return (i & ~7) | ((i & 3) << 1) | ((i >> 2) & 1);
}

// ---------------------------------------------------------------------------
// Kernel A: QKV projection via tf32 MMA. Q: [n][d] scaled; K: [n][perm(d)];
// V: transposed [d][perm(n)]. grid (18, 32, 3), block 128.
// ---------------------------------------------------------------------------
#define QS 68
__global__ void __launch_bounds__(128, 4) qkv_kernel(const float* __restrict__ x,
                           const float* __restrict__ Wq,
                           const float* __restrict__ Wk,
                           const float* __restrict__ Wv) {
    extern __shared__ float sm[];
    float* Xt  = sm;                 // [128 n][68]  (c inner), tf32
    float* Wsm = sm + 128 * QS;      // [64 d][68]   (c inner), tf32

    const int n0 = blockIdx.x * 128;
    const int hb = blockIdx.y;
    const int m  = blockIdx.z;

    const float* W   = (m == 0 ? Wq : (m == 1 ? Wk : Wv)) + (size_t)(hb >> 2) * HDIM * CIN;
    float*       out = (m == 0 ? g_q : (m == 1 ? g_k : g_v)) + (size_t)hb * NSP * HDIM;
    const float* xb  = x + (size_t)(hb & 3) * CIN * NSP;

    const int tid  = threadIdx.x;
    const int w    = tid >> 5;
    const int lane = tid & 31;
    const int gid  = lane >> 2;
    const int tig  = lane & 3;
    const int mr0  = w * 32;

    float acc[2][8][4];
    #pragma unroll
    for (int mt = 0; mt < 2; mt++)
        #pragma unroll
        for (int nt = 0; nt < 8; nt++)
            #pragma unroll
            for (int j = 0; j < 4; j++) acc[mt][nt][j] = 0.f;

    for (int c0 = 0; c0 < CIN; c0 += 64) {
        #pragma unroll
        for (int it = 0; it < 64; it++) {
            float v = xb[(size_t)(c0 + it) * NSP + n0 + tid];
            *(uint32_t*)&Xt[tid * QS + it] = f2tf(v);
        }
        #pragma unroll
        for (int ps = 0; ps < 8; ps++) {
            int idx = ps * 128 + tid;
            int d = idx >> 4, c4 = idx & 15;
            float4 wv = *(const float4*)&W[(size_t)d * CIN + c0 + c4 * 4];
            uint32_t* dst = (uint32_t*)&Wsm[d * QS + c4 * 4];
            dst[0] = f2tf(wv.x); dst[1] = f2tf(wv.y);
            dst[2] = f2tf(wv.z); dst[3] = f2tf(wv.w);
        }
        __syncthreads();

        #pragma unroll
        for (int kc = 0; kc < 8; kc++) {
            uint32_t afr[2][4];
            #pragma unroll
            for (int mt = 0; mt < 2; mt++) {
                const uint32_t* ar =
                    (const uint32_t*)&Xt[(mr0 + mt * 16 + gid) * QS + kc * 8 + tig];
                afr[mt][0] = ar[0];
                afr[mt][1] = ar[8 * QS];
                afr[mt][2] = ar[4];
                afr[mt][3] = ar[8 * QS + 4];
            }
            #pragma unroll
            for (int nt = 0; nt < 8; nt++) {
                const uint32_t* br =
                    (const uint32_t*)&Wsm[(nt * 8 + gid) * QS + kc * 8 + tig];
                uint32_t b0 = br[0], b1 = br[4];
                mma8(acc[0][nt], afr[0], b0, b1);
                mma8(acc[1][nt], afr[1], b0, b1);
            }
        }
        __syncthreads();
    }

    #pragma unroll
    for (int mt = 0; mt < 2; mt++) {
        int r0 = n0 + mr0 + mt * 16 + gid;
        if (m == 0) {
            // Q: [n][d], float2, tf32-rounded, pre-scaled
            #pragma unroll
            for (int nt = 0; nt < 8; nt++) {
                int d = nt * 8 + 2 * tig;
                *(float2*)&out[(size_t)r0 * HDIM + d] = make_float2(
                    tfv(acc[mt][nt][0] * QK_SCALE_L2E),
                    tfv(acc[mt][nt][1] * QK_SCALE_L2E));
                *(float2*)&out[(size_t)(r0 + 8) * HDIM + d] = make_float2(
                    tfv(acc[mt][nt][2] * QK_SCALE_L2E),
                    tfv(acc[mt][nt][3] * QK_SCALE_L2E));
            }
        } else if (m == 1) {
            // K: [n][perm(d)]
            #pragma unroll
            for (int nt = 0; nt < 8; nt++) {
                int d0 = nt * 8 + 2 * tig;
                int pd0 = perm8(d0), pd1 = perm8(d0 + 1);
                out[(size_t)r0 * HDIM + pd0]       = tfv(acc[mt][nt][0]);
                out[(size_t)r0 * HDIM + pd1]       = tfv(acc[mt][nt][1]);
                out[(size_t)(r0 + 8) * HDIM + pd0] = tfv(acc[mt][nt][2]);
                out[(size_t)(r0 + 8) * HDIM + pd1] = tfv(acc[mt][nt][3]);
            }
        } else {
            // V: transposed [d][perm(n)]
            int pn0 = perm8(r0);
            int pn1 = perm8(r0 + 8);   // same low-3 pattern, +8
            #pragma unroll
            for (int nt = 0; nt < 8; nt++) {
                int d0 = nt * 8 + 2 * tig;
                out[(size_t)d0 * NSP + pn0]       = tfv(acc[mt][nt][0]);
                out[(size_t)(d0 + 1) * NSP + pn0] = tfv(acc[mt][nt][1]);
                out[(size_t)d0 * NSP + pn1]       = tfv(acc[mt][nt][2]);
                out[(size_t)(d0 + 1) * NSP + pn1] = tfv(acc[mt][nt][3]);
            }
        }
    }
}

// ---------------------------------------------------------------------------
// Kernel B: tf32 warp-MMA flash attention, cp.async double-buffered K/V.
// CTA: 128 q-rows; 8 warps x 16 rows; k-tile 64; 36 iterations.
// K smem [64 n][68 perm-d]; V smem [64 d][68 perm-n]: B-fragments via LDS.64.
// smem: Ks[2][64][68] + Vs[2][64][68] + Ps[128][76] = 108.5KB -> 2 CTA/SM.
// grid (18, 32), block 256.
// ---------------------------------------------------------------------------
#define KSS 68
#define VSS 68
#define PSS 76
#define NKT (NSP / 64)

__device__ __forceinline__ void attn_issue_tile(const float* kg, const float* vg,
                                                float* Ks, float* Vs,
                                                int kt, int buf, int tid) {
    const float* ksrc = kg + (size_t)kt * 64 * HDIM;   // K rows = n
    const float* vsrc = vg + (size_t)kt * 64;          // V rows = d, col offset
    float* kdst = Ks + buf * 64 * KSS;
    float* vdst = Vs + buf * 64 * VSS;
    #pragma unroll
    for (int it = 0; it < 4; it++) {
        int idx = it * 256 + tid;
        int row = idx >> 4, c4 = (idx & 15) * 4;
        cp16(s2u(&kdst[row * KSS + c4]), ksrc + row * HDIM + c4);
    }
    #pragma unroll
    for (int it = 0; it < 4; it++) {
        int idx = it * 256 + tid;
        int row = idx >> 4, c4 = (idx & 15) * 4;
        cp16(s2u(&vdst[row * VSS + c4]), vsrc + (size_t)row * NSP + c4);
    }
    asm volatile("cp.async.commit_group;" ::: "memory");
}

__global__ void __launch_bounds__(256, 2) attn_kernel() {
    extern __shared__ float smem[];
    float* Ks = smem;                       // [2][64][68]
    float* Vs = smem + 2 * 64 * KSS;        // [2][64][68]
    float* Ps = smem + 2 * 64 * (KSS + VSS);// [128][76]

    const int qt = blockIdx.x;
    const int hb = blockIdx.y;
    const int h = hb >> 2, b = hb & 3;

    const float* qg = g_q + (size_t)hb * NSP * HDIM;
    const float* kg = g_k + (size_t)hb * NSP * HDIM;
    const float* vg = g_v + (size_t)hb * NSP * HDIM;

    const int tid  = threadIdx.x;
    const int w    = tid >> 5;
    const int lane = tid & 31;
    const int gid  = lane >> 2;
    const int tig  = lane & 3;
    const int rb   = w * 16;

    attn_issue_tile(kg, vg, Ks, Vs, 0, 0, tid);

    // Q fragments (already tf32 + scaled): plain bit loads
    uint32_t qa[8][4];
    {
        const uint32_t* qrow0 =
            (const uint32_t*)(qg + (size_t)(qt * 128 + rb + gid) * HDIM);
        const uint32_t* qrow1 = qrow0 + 8 * HDIM;
        #pragma unroll
        for (int kc = 0; kc < 8; kc++) {
            int c = kc * 8 + tig;
            qa[kc][0] = qrow0[c];
            qa[kc][1] = qrow1[c];
            qa[kc][2] = qrow0[c + 4];
            qa[kc][3] = qrow1[c + 4];
        }
    }

    float o[8][4];
    #pragma unroll
    for (int i = 0; i < 8; i++)
        #pragma unroll
        for (int j = 0; j < 4; j++) o[i][j] = 0.f;
    float sum0 = 0.f, sum1 = 0.f;

    for (int kt = 0; kt < NKT; kt++) {
        const int buf = kt & 1;
        asm volatile("cp.async.wait_group 0;" ::: "memory");
        __syncthreads();
        if (kt + 1 < NKT)
            attn_issue_tile(kg, vg, Ks, Vs, kt + 1, buf ^ 1, tid);

        const float* kb = Ks + buf * 64 * KSS;
        const float* vb = Vs + buf * 64 * VSS;

        // ---- S = Q @ K^T : one LDS.64 per B-fragment (perm layout)
        float s[8][4];
        #pragma unroll
        for (int nt = 0; nt < 8; nt++)
            #pragma unroll
            for (int j = 0; j < 4; j++) s[nt][j] = 0.f;

        #pragma unroll
        for (int kc = 0; kc < 8; kc++) {
            #pragma unroll
            for (int nt = 0; nt < 8; nt++) {
                uint2 b01 = *(const uint2*)&kb[(nt * 8 + gid) * KSS + kc * 8 + tig * 2];
                mma8(s[nt], qa[kc], b01.x, b01.y);
            }
        }

        // ---- softmax: exp2 only (scale+log2e folded into q); raw f32 to Ps
        #pragma unroll
        for (int nt = 0; nt < 8; nt++) {
            float e0 = exp2f(s[nt][0]);
            float e1 = exp2f(s[nt][1]);
            float e2 = exp2f(s[nt][2]);
            float e3 = exp2f(s[nt][3]);
            sum0 += e0 + e1;
            sum1 += e2 + e3;
            *(float2*)&Ps[(rb + gid) * PSS + nt * 8 + 2 * tig]     = make_float2(e0, e1);
            *(float2*)&Ps[(rb + gid + 8) * PSS + nt * 8 + 2 * tig] = make_float2(e2, e3);
        }
        __syncwarp();

        // ---- O += P @ V : one LDS.64 per B-fragment (transposed+perm V)
        #pragma unroll
        for (int kc = 0; kc < 8; kc++) {
            uint32_t pa[4];
            const float* p0 = &Ps[(rb + gid)     * PSS + kc * 8 + tig];
            const float* p1 = &Ps[(rb + gid + 8) * PSS + kc * 8 + tig];
            pa[0] = *(const uint32_t*)p0;
            pa[1] = *(const uint32_t*)p1;
            pa[2] = *(const uint32_t*)(p0 + 4);
            pa[3] = *(const uint32_t*)(p1 + 4);
            #pragma unroll
            for (int nt = 0; nt < 8; nt++) {
                uint2 v01 = *(const uint2*)&vb[(nt * 8 + gid) * VSS + kc * 8 + tig * 2];
                mma8(o[nt], pa, v01.x, v01.y);
            }
        }
        __syncthreads();   // all warps done with buf before it is refilled
    }

    sum0 += __shfl_xor_sync(0xffffffffu, sum0, 1);
    sum0 += __shfl_xor_sync(0xffffffffu, sum0, 2);
    sum1 += __shfl_xor_sync(0xffffffffu, sum1, 1);
    sum1 += __shfl_xor_sync(0xffffffffu, sum1, 2);
    const float inv0 = 1.0f / sum0;
    const float inv1 = 1.0f / sum1;

    // ws[h,n,b,d] -> wsr[(h>>1)*512 + (h&1)*256 + n/9][(n%9)*256 + b*64 + d]
    {
        const int n0 = qt * 128 + rb + gid;
        const int n1 = n0 + 8;
        const size_t ob0 = ((size_t)((h >> 1) * 512 + ((h & 1) << 8) + n0 / 9)) * NSP
                         + (n0 % 9) * 256 + b * 64;
        const size_t ob1 = ((size_t)((h >> 1) * 512 + ((h & 1) << 8) + n1 / 9)) * NSP
                         + (n1 % 9) * 256 + b * 64;
        #pragma unroll
        for (int nt = 0; nt < 8; nt++) {
            int d = nt * 8 + 2 * tig;
            *(float2*)&g_wsr[ob0 + d] = make_float2(o[nt][0] * inv0, o[nt][1] * inv0);
            *(float2*)&g_wsr[ob1 + d] = make_float2(o[nt][2] * inv1, o[nt][3] * inv1);
        }
    }
}

// ---------------------------------------------------------------------------
// Kernel C: output projection via tf32 MMA (unchanged winner).
// grid (18, 2, 4), block 256, dyn smem 69.6KB.
// ---------------------------------------------------------------------------
__global__ void __launch_bounds__(256, 2) oproj_kernel(const float* __restrict__ Wo,
                             float* __restrict__ out) {
    extern __shared__ float sm[];
    float* Wos = sm;                 // [128 o][68]
    float* Pt  = sm + 128 * QS;      // [128 p][68]

    const int p0 = blockIdx.x * 128;
    const int o0 = blockIdx.y * 128;
    const int b2 = blockIdx.z;
    const float* wsr = g_wsr + (size_t)b2 * 512 * NSP;

    const int tid  = threadIdx.x;
    const int w    = tid >> 5;
    const int lane = tid & 31;
    const int gid  = lane >> 2;
    const int tig  = lane & 3;
    const int mr0  = (w >> 1) * 32;
    const int nc0  = (w & 1) * 64;

    float acc[2][8][4];
    #pragma unroll
    for (int mt = 0; mt < 2; mt++)
        #pragma unroll
        for (int nt = 0; nt < 8; nt++)
            #pragma unroll
            for (int j = 0; j < 4; j++) acc[mt][nt][j] = 0.f;

    for (int c0 = 0; c0 < 512; c0 += 64) {
        #pragma unroll
        for (int ps = 0; ps < 8; ps++) {
            int idx = ps * 256 + tid;
            int o = idx >> 4, c4 = idx & 15;
            float4 wv = *(const float4*)&Wo[(size_t)(o0 + o) * 512 + c0 + c4 * 4];
            uint32_t* dst = (uint32_t*)&Wos[o * QS + c4 * 4];
            dst[0] = f2tf(wv.x); dst[1] = f2tf(wv.y);
            dst[2] = f2tf(wv.z); dst[3] = f2tf(wv.w);
        }
        #pragma unroll
        for (int it = 0; it < 32; it++) {
            int idx = it * 256 + tid;
            int p = idx & 127, c = idx >> 7;
            float v = wsr[(size_t)(c0 + c) * NSP + p0 + p];
            *(uint32_t*)&Pt[p * QS + c] = f2tf(v);
        }
        __syncthreads();

        #pragma unroll
        for (int kc = 0; kc < 8; kc++) {
            uint32_t afr[2][4];
            #pragma unroll
            for (int mt = 0; mt < 2; mt++) {
                const uint32_t* ar =
                    (const uint32_t*)&Wos[(mr0 + mt * 16 + gid) * QS + kc * 8 + tig];
                afr[mt][0] = ar[0];
                afr[mt][1] = ar[8 * QS];
                afr[mt][2] = ar[4];
                afr[mt][3] = ar[8 * QS + 4];
            }
            #pragma unroll
            for (int nt = 0; nt < 8; nt++) {
                const uint32_t* br =
                    (const uint32_t*)&Pt[(nc0 + nt * 8 + gid) * QS + kc * 8 + tig];
                uint32_t b0 = br[0], b1 = br[4];
                mma8(acc[0][nt], afr[0], b0, b1);
                mma8(acc[1][nt], afr[1], b0, b1);
            }
        }
        __syncthreads();
    }

    #pragma unroll
    for (int mt = 0; mt < 2; mt++) {
        int orow = o0 + mr0 + mt * 16 + gid;
        #pragma unroll
        for (int nt = 0; nt < 8; nt++) {
            int p = p0 + nc0 + nt * 8 + 2 * tig;
            *(float2*)&out[((size_t)(b2 * 256 + orow)) * NSP + p] =
                make_float2(acc[mt][nt][0], acc[mt][nt][1]);
            *(float2*)&out[((size_t)(b2 * 256 + orow + 8)) * NSP + p] =
                make_float2(acc[mt][nt][2], acc[mt][nt][3]);
        }
    }
}

// ---------------------------------------------------------------------------
extern "C" void kernel_launch(void* const* d_in, const int* in_sizes, int n_in,
                              void* d_out, int out_size) {
    const float* x  = (const float*)d_in[0];
    const float* Wq = (const float*)d_in[1];
    const float* Wk = (const float*)d_in[2];
    const float* Wv = (const float*)d_in[3];
    const float* Wo = (const float*)d_in[4];
    float* out = (float*)d_out;

    const int qkv_smem  = (128 * QS + 64 * QS) * 4;
    const int attn_smem = (2 * 64 * KSS + 2 * 64 * VSS + 128 * PSS) * 4; // 108544
    const int oprj_smem = (128 * QS + 128 * QS) * 4;

    cudaFuncSetAttribute(qkv_kernel,
                         cudaFuncAttributeMaxDynamicSharedMemorySize, qkv_smem);
    cudaFuncSetAttribute(attn_kernel,
                         cudaFuncAttributeMaxDynamicSharedMemorySize, attn_smem);
    cudaFuncSetAttribute(oproj_kernel,
                         cudaFuncAttributeMaxDynamicSharedMemorySize, oprj_smem);

    qkv_kernel<<<dim3(NSP / 128, HB, 3), 128, qkv_smem>>>(x, Wq, Wk, Wv);
    attn_kernel<<<dim3(NSP / 128, HB), 256, attn_smem>>>();
    oproj_kernel<<<dim3(NSP / 128, 2, 4), 256, oprj_smem>>>(Wo, out);
}

// round 12
// speedup vs baseline: 1.3064x; 1.3064x over previous
#include <cuda_runtime.h>
#include <cstdint>

#define NB   4
#define CIN  256
#define NSP  2304      // 48*48 tokens
#define NH   8
#define HDIM 64
#define HB   32        // NH*NB
// q pre-scale folds softmax scale AND log2(e): exp(s) == exp2(s')
#define QK_SCALE_L2E (0.125f * 1.44269504088896f)

typedef unsigned long long u64;

// Scratch (device globals — no allocations allowed)
// g_q: [hb][n][d], tf32-rounded, pre-scaled by 0.125*log2e
// g_k: [hb][n][d], tf32-rounded
// g_v: [hb][n][d], tf32-rounded
__device__ float g_q  [(size_t)HB * NSP * HDIM];
__device__ float g_k  [(size_t)HB * NSP * HDIM];
__device__ float g_v  [(size_t)HB * NSP * HDIM];
__device__ float g_wsr[(size_t)4 * 512 * NSP];   // scrambled ws: [b2][c][p]

// ---- helpers ---------------------------------------------------------------
__device__ __forceinline__ uint32_t f2tf(float f) {
    uint32_t r;
    asm("cvt.rna.tf32.f32 %0, %1;" : "=r"(r) : "f"(f));
    return r;
}
__device__ __forceinline__ float tfv(float f) { return __uint_as_float(f2tf(f)); }
__device__ __forceinline__ float ex2(float x) {
    float r;
    asm("ex2.approx.f32 %0, %1;" : "=f"(r) : "f"(x));
    return r;
}
__device__ __forceinline__ void mma8(float* d, const uint32_t* a,
                                     uint32_t b0, uint32_t b1) {
    asm volatile(
        "mma.sync.aligned.m16n8k8.row.col.f32.tf32.tf32.f32 "
        "{%0,%1,%2,%3}, {%4,%5,%6,%7}, {%8,%9}, {%0,%1,%2,%3};"
        : "+f"(d[0]), "+f"(d[1]), "+f"(d[2]), "+f"(d[3])
        : "r"(a[0]), "r"(a[1]), "r"(a[2]), "r"(a[3]), "r"(b0), "r"(b1));
}
__device__ __forceinline__ uint32_t s2u(const void* p) {
    return (uint32_t)__cvta_generic_to_shared(p);
}
__device__ __forceinline__ void cp16(uint32_t smem_dst, const void* gsrc) {
    asm volatile("cp.async.cg.shared.global [%0], [%1], 16;"
                 :: "r"(smem_dst), "l"(gsrc));
}

// ---------------------------------------------------------------------------
// Kernel A: QKV projection via tf32 MMA. Outputs tf32-rounded [n][d];
// q additionally pre-scaled by 0.125*log2e. grid (18, 32, 3), block 128.
// ---------------------------------------------------------------------------
#define QS 68
__global__ void __launch_bounds__(128, 4) qkv_kernel(const float* __restrict__ x,
                           const float* __restrict__ Wq,
                           const float* __restrict__ Wk,
                           const float* __restrict__ Wv) {
    extern __shared__ float sm[];
    float* Xt  = sm;                 // [128 n][68]  (c inner), tf32
    float* Wsm = sm + 128 * QS;      // [64 d][68]   (c inner), tf32

    const int n0 = blockIdx.x * 128;
    const int hb = blockIdx.y;
    const int m  = blockIdx.z;

    const float* W   = (m == 0 ? Wq : (m == 1 ? Wk : Wv)) + (size_t)(hb >> 2) * HDIM * CIN;
    float*       out = (m == 0 ? g_q : (m == 1 ? g_k : g_v)) + (size_t)hb * NSP * HDIM;
    const float* xb  = x + (size_t)(hb & 3) * CIN * NSP;
    const float oscale = (m == 0) ? QK_SCALE_L2E : 1.0f;

    const int tid  = threadIdx.x;
    const int w    = tid >> 5;
    const int lane = tid & 31;
    const int gid  = lane >> 2;
    const int tig  = lane & 3;
    const int mr0  = w * 32;

    float acc[2][8][4];
    #pragma unroll
    for (int mt = 0; mt < 2; mt++)
        #pragma unroll
        for (int nt = 0; nt < 8; nt++)
            #pragma unroll
            for (int j = 0; j < 4; j++) acc[mt][nt][j] = 0.f;

    for (int c0 = 0; c0 < CIN; c0 += 64) {
        #pragma unroll
        for (int it = 0; it < 64; it++) {
            float v = xb[(size_t)(c0 + it) * NSP + n0 + tid];
            *(uint32_t*)&Xt[tid * QS + it] = f2tf(v);
        }
        #pragma unroll
        for (int ps = 0; ps < 8; ps++) {
            int idx = ps * 128 + tid;
            int d = idx >> 4, c4 = idx & 15;
            float4 wv = *(const float4*)&W[(size_t)d * CIN + c0 + c4 * 4];
            uint32_t* dst = (uint32_t*)&Wsm[d * QS + c4 * 4];
            dst[0] = f2tf(wv.x); dst[1] = f2tf(wv.y);
            dst[2] = f2tf(wv.z); dst[3] = f2tf(wv.w);
        }
        __syncthreads();

        #pragma unroll
        for (int kc = 0; kc < 8; kc++) {
            uint32_t afr[2][4];
            #pragma unroll
            for (int mt = 0; mt < 2; mt++) {
                const uint32_t* ar =
                    (const uint32_t*)&Xt[(mr0 + mt * 16 + gid) * QS + kc * 8 + tig];
                afr[mt][0] = ar[0];
                afr[mt][1] = ar[8 * QS];
                afr[mt][2] = ar[4];
                afr[mt][3] = ar[8 * QS + 4];
            }
            #pragma unroll
            for (int nt = 0; nt < 8; nt++) {
                const uint32_t* br =
                    (const uint32_t*)&Wsm[(nt * 8 + gid) * QS + kc * 8 + tig];
                uint32_t b0 = br[0], b1 = br[4];
                mma8(acc[0][nt], afr[0], b0, b1);
                mma8(acc[1][nt], afr[1], b0, b1);
            }
        }
        __syncthreads();
    }

    #pragma unroll
    for (int mt = 0; mt < 2; mt++) {
        int r0 = n0 + mr0 + mt * 16 + gid;
        #pragma unroll
        for (int nt = 0; nt < 8; nt++) {
            int d = nt * 8 + 2 * tig;
            *(float2*)&out[(size_t)r0 * HDIM + d] = make_float2(
                tfv(acc[mt][nt][0] * oscale),
                tfv(acc[mt][nt][1] * oscale));
            *(float2*)&out[(size_t)(r0 + 8) * HDIM + d] = make_float2(
                tfv(acc[mt][nt][2] * oscale),
                tfv(acc[mt][nt][3] * oscale));
        }
    }
}

// ---------------------------------------------------------------------------
// Kernel B: tf32 warp-MMA flash attention, cp.async double-buffered K/V.
// CTA: 128 q-rows; 8 warps x 16 rows; k-tile 64; 36 iterations.
// R10 layouts (all conflict-free LDS.32). Ps stride 76 (fixes 2-way conflict).
// Single barrier per iteration (end-of-loop sync proved redundant).
// smem: Ks[2][64][68] + Vs[2][64][72] + Ps[128][76] = 110592 B -> 2 CTA/SM.
// grid (18, 32), block 256.
// ---------------------------------------------------------------------------
#define KSS 68
#define VSS 72
#define PSS 76
#define NKT (NSP / 64)

__device__ __forceinline__ void attn_issue_tile(const float* kg, const float* vg,
                                                float* Ks, float* Vs,
                                                int kt, int buf, int tid) {
    const float* ksrc = kg + (size_t)kt * 64 * HDIM;
    const float* vsrc = vg + (size_t)kt * 64 * HDIM;
    float* kdst = Ks + buf * 64 * KSS;
    float* vdst = Vs + buf * 64 * VSS;
    #pragma unroll
    for (int it = 0; it < 4; it++) {
        int idx = it * 256 + tid;
        int row = idx >> 4, c4 = (idx & 15) * 4;
        cp16(s2u(&kdst[row * KSS + c4]), ksrc + row * HDIM + c4);
    }
    #pragma unroll
    for (int it = 0; it < 4; it++) {
        int idx = it * 256 + tid;
        int row = idx >> 4, c4 = (idx & 15) * 4;
        cp16(s2u(&vdst[row * VSS + c4]), vsrc + row * HDIM + c4);
    }
    asm volatile("cp.async.commit_group;" ::: "memory");
}

__global__ void __launch_bounds__(256, 2) attn_kernel() {
    extern __shared__ float smem[];
    float* Ks = smem;                       // [2][64][68]
    float* Vs = smem + 2 * 64 * KSS;        // [2][64][72]
    float* Ps = smem + 2 * 64 * (KSS + VSS);// [128][76]

    const int qt = blockIdx.x;
    const int hb = blockIdx.y;
    const int h = hb >> 2, b = hb & 3;

    const float* qg = g_q + (size_t)hb * NSP * HDIM;
    const float* kg = g_k + (size_t)hb * NSP * HDIM;
    const float* vg = g_v + (size_t)hb * NSP * HDIM;

    const int tid  = threadIdx.x;
    const int w    = tid >> 5;
    const int lane = tid & 31;
    const int gid  = lane >> 2;
    const int tig  = lane & 3;
    const int rb   = w * 16;

    attn_issue_tile(kg, vg, Ks, Vs, 0, 0, tid);

    // Q fragments (already tf32 + scaled): plain bit loads
    uint32_t qa[8][4];
    {
        const uint32_t* qrow0 =
            (const uint32_t*)(qg + (size_t)(qt * 128 + rb + gid) * HDIM);
        const uint32_t* qrow1 = qrow0 + 8 * HDIM;
        #pragma unroll
        for (int kc = 0; kc < 8; kc++) {
            int c = kc * 8 + tig;
            qa[kc][0] = qrow0[c];
            qa[kc][1] = qrow1[c];
            qa[kc][2] = qrow0[c + 4];
            qa[kc][3] = qrow1[c + 4];
        }
    }

    float o[8][4];
    #pragma unroll
    for (int i = 0; i < 8; i++)
        #pragma unroll
        for (int j = 0; j < 4; j++) o[i][j] = 0.f;
    float sum0 = 0.f, sum1 = 0.f;

    for (int kt = 0; kt < NKT; kt++) {
        const int buf = kt & 1;
        asm volatile("cp.async.wait_group 0;" ::: "memory");
        __syncthreads();   // all threads' copies for buf complete; prev compute done
        if (kt + 1 < NKT)
            attn_issue_tile(kg, vg, Ks, Vs, kt + 1, buf ^ 1, tid);

        const float* kb = Ks + buf * 64 * KSS;
        const float* vb = Vs + buf * 64 * VSS;

        // ---- S = Q @ K^T : 16 x 64 per warp (conflict-free LDS.32 pairs)
        float s[8][4];
        #pragma unroll
        for (int nt = 0; nt < 8; nt++)
            #pragma unroll
            for (int j = 0; j < 4; j++) s[nt][j] = 0.f;

        #pragma unroll
        for (int kc = 0; kc < 8; kc++) {
            #pragma unroll
            for (int nt = 0; nt < 8; nt++) {
                const uint32_t* krow =
                    (const uint32_t*)&kb[(nt * 8 + gid) * KSS + kc * 8 + tig];
                mma8(s[nt], qa[kc], krow[0], krow[4]);
            }
        }

        // ---- softmax: single MUFU (scale+log2e pre-folded); raw f32 P
        #pragma unroll
        for (int nt = 0; nt < 8; nt++) {
            float e0 = ex2(s[nt][0]);
            float e1 = ex2(s[nt][1]);
            float e2 = ex2(s[nt][2]);
            float e3 = ex2(s[nt][3]);
            sum0 += e0 + e1;
            sum1 += e2 + e3;
            *(float2*)&Ps[(rb + gid) * PSS + nt * 8 + 2 * tig]     = make_float2(e0, e1);
            *(float2*)&Ps[(rb + gid + 8) * PSS + nt * 8 + 2 * tig] = make_float2(e2, e3);
        }
        __syncwarp();

        // ---- O += P @ V : V read (kpos,d) row-major, conflict-free
        #pragma unroll
        for (int kc = 0; kc < 8; kc++) {
            uint32_t pa[4];
            const float* p0 = &Ps[(rb + gid)     * PSS + kc * 8 + tig];
            const float* p1 = &Ps[(rb + gid + 8) * PSS + kc * 8 + tig];
            pa[0] = *(const uint32_t*)p0;
            pa[1] = *(const uint32_t*)p1;
            pa[2] = *(const uint32_t*)(p0 + 4);
            pa[3] = *(const uint32_t*)(p1 + 4);
            #pragma unroll
            for (int nt = 0; nt < 8; nt++) {
                const uint32_t* vrow =
                    (const uint32_t*)&vb[(kc * 8 + tig) * VSS + nt * 8 + gid];
                mma8(o[nt], pa, vrow[0], vrow[4 * VSS]);
            }
        }
        // no end-of-loop barrier: next iteration's wait+sync provides ordering
    }

    sum0 += __shfl_xor_sync(0xffffffffu, sum0, 1);
    sum0 += __shfl_xor_sync(0xffffffffu, sum0, 2);
    sum1 += __shfl_xor_sync(0xffffffffu, sum1, 1);
    sum1 += __shfl_xor_sync(0xffffffffu, sum1, 2);
    const float inv0 = 1.0f / sum0;
    const float inv1 = 1.0f / sum1;

    // ws[h,n,b,d] -> wsr[(h>>1)*512 + (h&1)*256 + n/9][(n%9)*256 + b*64 + d]
    {
        const int n0 = qt * 128 + rb + gid;
        const int n1 = n0 + 8;
        const size_t ob0 = ((size_t)((h >> 1) * 512 + ((h & 1) << 8) + n0 / 9)) * NSP
                         + (n0 % 9) * 256 + b * 64;
        const size_t ob1 = ((size_t)((h >> 1) * 512 + ((h & 1) << 8) + n1 / 9)) * NSP
                         + (n1 % 9) * 256 + b * 64;
        #pragma unroll
        for (int nt = 0; nt < 8; nt++) {
            int d = nt * 8 + 2 * tig;
            *(float2*)&g_wsr[ob0 + d] = make_float2(o[nt][0] * inv0, o[nt][1] * inv0);
            *(float2*)&g_wsr[ob1 + d] = make_float2(o[nt][2] * inv1, o[nt][3] * inv1);
        }
    }
}

// ---------------------------------------------------------------------------
// Kernel C: output projection via tf32 MMA (unchanged winner).
// grid (18, 2, 4), block 256, dyn smem 69.6KB.
// ---------------------------------------------------------------------------
__global__ void __launch_bounds__(256, 2) oproj_kernel(const float* __restrict__ Wo,
                             float* __restrict__ out) {
    extern __shared__ float sm[];
    float* Wos = sm;                 // [128 o][68]
    float* Pt  = sm + 128 * QS;      // [128 p][68]

    const int p0 = blockIdx.x * 128;
    const int o0 = blockIdx.y * 128;
    const int b2 = blockIdx.z;
    const float* wsr = g_wsr + (size_t)b2 * 512 * NSP;

    const int tid  = threadIdx.x;
    const int w    = tid >> 5;
    const int lane = tid & 31;
    const int gid  = lane >> 2;
    const int tig  = lane & 3;
    const int mr0  = (w >> 1) * 32;
    const int nc0  = (w & 1) * 64;

    float acc[2][8][4];
    #pragma unroll
    for (int mt = 0; mt < 2; mt++)
        #pragma unroll
        for (int nt = 0; nt < 8; nt++)
            #pragma unroll
            for (int j = 0; j < 4; j++) acc[mt][nt][j] = 0.f;

    for (int c0 = 0; c0 < 512; c0 += 64) {
        #pragma unroll
        for (int ps = 0; ps < 8; ps++) {
            int idx = ps * 256 + tid;
            int o = idx >> 4, c4 = idx & 15;
            float4 wv = *(const float4*)&Wo[(size_t)(o0 + o) * 512 + c0 + c4 * 4];
            uint32_t* dst = (uint32_t*)&Wos[o * QS + c4 * 4];
            dst[0] = f2tf(wv.x); dst[1] = f2tf(wv.y);
            dst[2] = f2tf(wv.z); dst[3] = f2tf(wv.w);
        }
        #pragma unroll
        for (int it = 0; it < 32; it++) {
            int idx = it * 256 + tid;
            int p = idx & 127, c = idx >> 7;
            float v = wsr[(size_t)(c0 + c) * NSP + p0 + p];
            *(uint32_t*)&Pt[p * QS + c] = f2tf(v);
        }
        __syncthreads();

        #pragma unroll
        for (int kc = 0; kc < 8; kc++) {
            uint32_t afr[2][4];
            #pragma unroll
            for (int mt = 0; mt < 2; mt++) {
                const uint32_t* ar =
                    (const uint32_t*)&Wos[(mr0 + mt * 16 + gid) * QS + kc * 8 + tig];
                afr[mt][0] = ar[0];
                afr[mt][1] = ar[8 * QS];
                afr[mt][2] = ar[4];
                afr[mt][3] = ar[8 * QS + 4];
            }
            #pragma unroll
            for (int nt = 0; nt < 8; nt++) {
                const uint32_t* br =
                    (const uint32_t*)&Pt[(nc0 + nt * 8 + gid) * QS + kc * 8 + tig];
                uint32_t b0 = br[0], b1 = br[4];
                mma8(acc[0][nt], afr[0], b0, b1);
                mma8(acc[1][nt], afr[1], b0, b1);
            }
        }
        __syncthreads();
    }

    #pragma unroll
    for (int mt = 0; mt < 2; mt++) {
        int orow = o0 + mr0 + mt * 16 + gid;
        #pragma unroll
        for (int nt = 0; nt < 8; nt++) {
            int p = p0 + nc0 + nt * 8 + 2 * tig;
            *(float2*)&out[((size_t)(b2 * 256 + orow)) * NSP + p] =
                make_float2(acc[mt][nt][0], acc[mt][nt][1]);
            *(float2*)&out[((size_t)(b2 * 256 + orow + 8)) * NSP + p] =
                make_float2(acc[mt][nt][2], acc[mt][nt][3]);
        }
    }
}

// ---------------------------------------------------------------------------
extern "C" void kernel_launch(void* const* d_in, const int* in_sizes, int n_in,
                              void* d_out, int out_size) {
    const float* x  = (const float*)d_in[0];
    const float* Wq = (const float*)d_in[1];
    const float* Wk = (const float*)d_in[2];
    const float* Wv = (const float*)d_in[3];
    const float* Wo = (const float*)d_in[4];
    float* out = (float*)d_out;

    const int qkv_smem  = (128 * QS + 64 * QS) * 4;
    const int attn_smem = (2 * 64 * KSS + 2 * 64 * VSS + 128 * PSS) * 4; // 110592
    const int oprj_smem = (128 * QS + 128 * QS) * 4;

    cudaFuncSetAttribute(qkv_kernel,
                         cudaFuncAttributeMaxDynamicSharedMemorySize, qkv_smem);
    cudaFuncSetAttribute(attn_kernel,
                         cudaFuncAttributeMaxDynamicSharedMemorySize, attn_smem);
    cudaFuncSetAttribute(oproj_kernel,
                         cudaFuncAttributeMaxDynamicSharedMemorySize, oprj_smem);

    qkv_kernel<<<dim3(NSP / 128, HB, 3), 128, qkv_smem>>>(x, Wq, Wk, Wv);
    attn_kernel<<<dim3(NSP / 128, HB), 256, attn_smem>>>();
    oproj_kernel<<<dim3(NSP / 128, 2, 4), 256, oprj_smem>>>(Wo, out);
}

// round 13
// speedup vs baseline: 2.0535x; 1.5719x over previous
#include <cuda_runtime.h>
#include <cuda_fp16.h>
#include <cstdint>

#define NB   4
#define CIN  256
#define NSP  2304      // 48*48 tokens
#define NH   8
#define HDIM 64
#define HB   32        // NH*NB
// q pre-scale folds softmax scale AND log2(e): exp(s) == exp2(s')
#define QK_SCALE_L2E (0.125f * 1.44269504088896f)

typedef unsigned long long u64;

// Scratch (device globals — no allocations allowed)
// g_q: fp16 [hb][n][d], pre-scaled by 0.125*log2e
// g_k: fp16 [hb][n][d]
// g_v: fp16 [hb][d][n]  (TRANSPOSED for PV .col B-fragments)
__device__ __half g_q  [(size_t)HB * NSP * HDIM];
__device__ __half g_k  [(size_t)HB * NSP * HDIM];
__device__ __half g_v  [(size_t)HB * NSP * HDIM];
__device__ float  g_wsr[(size_t)4 * 512 * NSP];   // scrambled ws: [b2][c][p]

// ---- helpers ---------------------------------------------------------------
__device__ __forceinline__ uint32_t f2tf(float f) {
    uint32_t r;
    asm("cvt.rna.tf32.f32 %0, %1;" : "=r"(r) : "f"(f));
    return r;
}
__device__ __forceinline__ float ex2(float x) {
    float r;
    asm("ex2.approx.f32 %0, %1;" : "=f"(r) : "f"(x));
    return r;
}
// tf32 k8 mma (qkv / oproj)
__device__ __forceinline__ void mma8(float* d, const uint32_t* a,
                                     uint32_t b0, uint32_t b1) {
    asm volatile(
        "mma.sync.aligned.m16n8k8.row.col.f32.tf32.tf32.f32 "
        "{%0,%1,%2,%3}, {%4,%5,%6,%7}, {%8,%9}, {%0,%1,%2,%3};"
        : "+f"(d[0]), "+f"(d[1]), "+f"(d[2]), "+f"(d[3])
        : "r"(a[0]), "r"(a[1]), "r"(a[2]), "r"(a[3]), "r"(b0), "r"(b1));
}
// fp16 k16 mma (attention)
__device__ __forceinline__ void mma16(float* d, const uint32_t* a,
                                      uint32_t b0, uint32_t b1) {
    asm volatile(
        "mma.sync.aligned.m16n8k16.row.col.f32.f16.f16.f32 "
        "{%0,%1,%2,%3}, {%4,%5,%6,%7}, {%8,%9}, {%0,%1,%2,%3};"
        : "+f"(d[0]), "+f"(d[1]), "+f"(d[2]), "+f"(d[3])
        : "r"(a[0]), "r"(a[1]), "r"(a[2]), "r"(a[3]), "r"(b0), "r"(b1));
}
__device__ __forceinline__ uint32_t s2u(const void* p) {
    return (uint32_t)__cvta_generic_to_shared(p);
}
__device__ __forceinline__ void cp16(uint32_t smem_dst, const void* gsrc) {
    asm volatile("cp.async.cg.shared.global [%0], [%1], 16;"
                 :: "r"(smem_dst), "l"(gsrc));
}
__device__ __forceinline__ uint32_t packh2(float lo, float hi) {
    __half2 h = __floats2half2_rn(lo, hi);
    return *(uint32_t*)&h;
}

// ---------------------------------------------------------------------------
// Kernel A: QKV projection via tf32 MMA, fp16 outputs.
// Q/K: fp16 [n][d] (q pre-scaled by 0.125*log2e); V: fp16 [d][n] transposed.
// grid (18, 32, 3), block 128, dyn smem 52.2KB.
// ---------------------------------------------------------------------------
#define QS 68
__global__ void __launch_bounds__(128, 4) qkv_kernel(const float* __restrict__ x,
                           const float* __restrict__ Wq,
                           const float* __restrict__ Wk,
                           const float* __restrict__ Wv) {
    extern __shared__ float sm[];
    float* Xt  = sm;                 // [128 n][68]  (c inner), tf32
    float* Wsm = sm + 128 * QS;      // [64 d][68]   (c inner), tf32

    const int n0 = blockIdx.x * 128;
    const int hb = blockIdx.y;
    const int m  = blockIdx.z;

    const float* W   = (m == 0 ? Wq : (m == 1 ? Wk : Wv)) + (size_t)(hb >> 2) * HDIM * CIN;
    __half*      out = (m == 0 ? g_q : (m == 1 ? g_k : g_v)) + (size_t)hb * NSP * HDIM;
    const float* xb  = x + (size_t)(hb & 3) * CIN * NSP;
    const float oscale = (m == 0) ? QK_SCALE_L2E : 1.0f;

    const int tid  = threadIdx.x;
    const int w    = tid >> 5;
    const int lane = tid & 31;
    const int gid  = lane >> 2;
    const int tig  = lane & 3;
    const int mr0  = w * 32;

    float acc[2][8][4];
    #pragma unroll
    for (int mt = 0; mt < 2; mt++)
        #pragma unroll
        for (int nt = 0; nt < 8; nt++)
            #pragma unroll
            for (int j = 0; j < 4; j++) acc[mt][nt][j] = 0.f;

    for (int c0 = 0; c0 < CIN; c0 += 64) {
        #pragma unroll
        for (int it = 0; it < 64; it++) {
            float v = xb[(size_t)(c0 + it) * NSP + n0 + tid];
            *(uint32_t*)&Xt[tid * QS + it] = f2tf(v);
        }
        #pragma unroll
        for (int ps = 0; ps < 8; ps++) {
            int idx = ps * 128 + tid;
            int d = idx >> 4, c4 = idx & 15;
            float4 wv = *(const float4*)&W[(size_t)d * CIN + c0 + c4 * 4];
            uint32_t* dst = (uint32_t*)&Wsm[d * QS + c4 * 4];
            dst[0] = f2tf(wv.x); dst[1] = f2tf(wv.y);
            dst[2] = f2tf(wv.z); dst[3] = f2tf(wv.w);
        }
        __syncthreads();

        #pragma unroll
        for (int kc = 0; kc < 8; kc++) {
            uint32_t afr[2][4];
            #pragma unroll
            for (int mt = 0; mt < 2; mt++) {
                const uint32_t* ar =
                    (const uint32_t*)&Xt[(mr0 + mt * 16 + gid) * QS + kc * 8 + tig];
                afr[mt][0] = ar[0];
                afr[mt][1] = ar[8 * QS];
                afr[mt][2] = ar[4];
                afr[mt][3] = ar[8 * QS + 4];
            }
            #pragma unroll
            for (int nt = 0; nt < 8; nt++) {
                const uint32_t* br =
                    (const uint32_t*)&Wsm[(nt * 8 + gid) * QS + kc * 8 + tig];
                uint32_t b0 = br[0], b1 = br[4];
                mma8(acc[0][nt], afr[0], b0, b1);
                mma8(acc[1][nt], afr[1], b0, b1);
            }
        }
        __syncthreads();
    }

    #pragma unroll
    for (int mt = 0; mt < 2; mt++) {
        int r0 = n0 + mr0 + mt * 16 + gid;
        if (m != 2) {
            // Q/K: fp16 [n][d]; cols d = nt*8+2tig pair -> half2 word nt*4+tig
            uint32_t* o0 = (uint32_t*)(out + (size_t)r0 * HDIM);
            uint32_t* o1 = (uint32_t*)(out + (size_t)(r0 + 8) * HDIM);
            #pragma unroll
            for (int nt = 0; nt < 8; nt++) {
                o0[nt * 4 + tig] = packh2(acc[mt][nt][0] * oscale,
                                          acc[mt][nt][1] * oscale);
                o1[nt * 4 + tig] = packh2(acc[mt][nt][2] * oscale,
                                          acc[mt][nt][3] * oscale);
            }
        } else {
            // V: fp16 [d][n] transposed, scalar scatter
            #pragma unroll
            for (int nt = 0; nt < 8; nt++) {
                int d = nt * 8 + 2 * tig;
                out[(size_t)d * NSP + r0]           = __float2half(acc[mt][nt][0]);
                out[(size_t)(d + 1) * NSP + r0]     = __float2half(acc[mt][nt][1]);
                out[(size_t)d * NSP + r0 + 8]       = __float2half(acc[mt][nt][2]);
                out[(size_t)(d + 1) * NSP + r0 + 8] = __float2half(acc[mt][nt][3]);
            }
        }
    }
}

// ---------------------------------------------------------------------------
// Kernel B: fp16 m16n8k16 flash attention, cp.async double-buffered K/V.
// CTA: 128 q-rows; 8 warps x 16 rows; k-tile 64; 36 iterations.
// K smem [64 kpos][36w fp16x2]; V^T smem [64 d][36w]; Ps [128][36w] fp16x2.
// All fragment LDS conflict-free (bank 4g+t / +4). smem 54KB -> 2 CTA/SM.
// grid (18, 32), block 256.
// ---------------------------------------------------------------------------
#define KS2 36
#define VS2 36
#define PS2 36
#define NKT (NSP / 64)

__device__ __forceinline__ void attn_issue_tile(const __half* kg, const __half* vg,
                                                uint32_t* Ks, uint32_t* Vs,
                                                int kt, int buf, int tid) {
    const __half* ksrc = kg + (size_t)kt * 64 * HDIM;   // rows kpos, 64 fp16 each
    const __half* vsrc = vg + (size_t)kt * 64;          // rows d, col offset kt*64
    uint32_t* kdst = Ks + buf * 64 * KS2;
    uint32_t* vdst = Vs + buf * 64 * VS2;
    #pragma unroll
    for (int it = 0; it < 2; it++) {
        int idx = it * 256 + tid;
        int row = idx >> 3, c4 = idx & 7;      // 8 x 16B chunks per 128B row
        cp16(s2u(&kdst[row * KS2 + c4 * 4]), ksrc + row * HDIM + c4 * 8);
    }
    #pragma unroll
    for (int it = 0; it < 2; it++) {
        int idx = it * 256 + tid;
        int row = idx >> 3, c4 = idx & 7;
        cp16(s2u(&vdst[row * VS2 + c4 * 4]), vsrc + (size_t)row * NSP + c4 * 8);
    }
    asm volatile("cp.async.commit_group;" ::: "memory");
}

__global__ void __launch_bounds__(256, 2) attn_kernel() {
    extern __shared__ uint32_t smw[];
    uint32_t* Ks = smw;                         // [2][64][36]
    uint32_t* Vs = smw + 2 * 64 * KS2;          // [2][64][36]
    uint32_t* Ps = smw + 2 * 64 * (KS2 + VS2);  // [128][36]

    const int qt = blockIdx.x;
    const int hb = blockIdx.y;
    const int h = hb >> 2, b = hb & 3;

    const __half* qg = g_q + (size_t)hb * NSP * HDIM;
    const __half* kg = g_k + (size_t)hb * NSP * HDIM;
    const __half* vg = g_v + (size_t)hb * NSP * HDIM;

    const int tid  = threadIdx.x;
    const int w    = tid >> 5;
    const int lane = tid & 31;
    const int gid  = lane >> 2;
    const int tig  = lane & 3;
    const int rb   = w * 16;

    attn_issue_tile(kg, vg, Ks, Vs, 0, 0, tid);

    // Q A-fragments (fp16x2 words): rows rb+gid / rb+gid+8, 4 k16-chunks
    uint32_t qa[4][4];
    {
        const uint32_t* qw0 =
            (const uint32_t*)(qg + (size_t)(qt * 128 + rb + gid) * HDIM);
        const uint32_t* qw1 = qw0 + 8 * (HDIM / 2);
        #pragma unroll
        for (int kc = 0; kc < 4; kc++) {
            qa[kc][0] = qw0[kc * 8 + tig];
            qa[kc][1] = qw1[kc * 8 + tig];
            qa[kc][2] = qw0[kc * 8 + tig + 4];
            qa[kc][3] = qw1[kc * 8 + tig + 4];
        }
    }

    float o[8][4];
    #pragma unroll
    for (int i = 0; i < 8; i++)
        #pragma unroll
        for (int j = 0; j < 4; j++) o[i][j] = 0.f;
    float sum0 = 0.f, sum1 = 0.f;

    for (int kt = 0; kt < NKT; kt++) {
        const int buf = kt & 1;
        asm volatile("cp.async.wait_group 0;" ::: "memory");
        __syncthreads();
        if (kt + 1 < NKT)
            attn_issue_tile(kg, vg, Ks, Vs, kt + 1, buf ^ 1, tid);

        const uint32_t* kb = Ks + buf * 64 * KS2;
        const uint32_t* vb = Vs + buf * 64 * VS2;

        // ---- S = Q @ K^T : 16 x 64 per warp, k=d in 4 chunks of 16
        float s[8][4];
        #pragma unroll
        for (int nt = 0; nt < 8; nt++)
            #pragma unroll
            for (int j = 0; j < 4; j++) s[nt][j] = 0.f;

        #pragma unroll
        for (int kc = 0; kc < 4; kc++) {
            #pragma unroll
            for (int nt = 0; nt < 8; nt++) {
                const uint32_t* krow = &kb[(nt * 8 + gid) * KS2 + kc * 8 + tig];
                mma16(s[nt], qa[kc], krow[0], krow[4]);
            }
        }

        // ---- softmax: ex2 (pre-folded scale), f32 sums, fp16x2 P store
        #pragma unroll
        for (int nt = 0; nt < 8; nt++) {
            float e0 = ex2(s[nt][0]);
            float e1 = ex2(s[nt][1]);
            float e2 = ex2(s[nt][2]);
            float e3 = ex2(s[nt][3]);
            sum0 += e0 + e1;
            sum1 += e2 + e3;
            Ps[(rb + gid) * PS2 + nt * 4 + tig]     = packh2(e0, e1);
            Ps[(rb + gid + 8) * PS2 + nt * 4 + tig] = packh2(e2, e3);
        }
        __syncwarp();

        // ---- O += P @ V : k=kpos in 4 chunks of 16, V^T rows = d
        #pragma unroll
        for (int kc = 0; kc < 4; kc++) {
            uint32_t pa[4];
            pa[0] = Ps[(rb + gid) * PS2 + kc * 8 + tig];
            pa[1] = Ps[(rb + gid + 8) * PS2 + kc * 8 + tig];
            pa[2] = Ps[(rb + gid) * PS2 + kc * 8 + tig + 4];
            pa[3] = Ps[(rb + gid + 8) * PS2 + kc * 8 + tig + 4];
            #pragma unroll
            for (int nt = 0; nt < 8; nt++) {
                const uint32_t* vrow = &vb[(nt * 8 + gid) * VS2 + kc * 8 + tig];
                mma16(o[nt], pa, vrow[0], vrow[4]);
            }
        }
        // no end-of-loop barrier: next iteration's wait+sync provides ordering
    }

    sum0 += __shfl_xor_sync(0xffffffffu, sum0, 1);
    sum0 += __shfl_xor_sync(0xffffffffu, sum0, 2);
    sum1 += __shfl_xor_sync(0xffffffffu, sum1, 1);
    sum1 += __shfl_xor_sync(0xffffffffu, sum1, 2);
    const float inv0 = 1.0f / sum0;
    const float inv1 = 1.0f / sum1;

    // ws[h,n,b,d] -> wsr[(h>>1)*512 + (h&1)*256 + n/9][(n%9)*256 + b*64 + d]
    {
        const int n0 = qt * 128 + rb + gid;
        const int n1 = n0 + 8;
        const size_t ob0 = ((size_t)((h >> 1) * 512 + ((h & 1) << 8) + n0 / 9)) * NSP
                         + (n0 % 9) * 256 + b * 64;
        const size_t ob1 = ((size_t)((h >> 1) * 512 + ((h & 1) << 8) + n1 / 9)) * NSP
                         + (n1 % 9) * 256 + b * 64;
        #pragma unroll
        for (int nt = 0; nt < 8; nt++) {
            int d = nt * 8 + 2 * tig;
            *(float2*)&g_wsr[ob0 + d] = make_float2(o[nt][0] * inv0, o[nt][1] * inv0);
            *(float2*)&g_wsr[ob1 + d] = make_float2(o[nt][2] * inv1, o[nt][3] * inv1);
        }
    }
}

// ---------------------------------------------------------------------------
// Kernel C: output projection via tf32 MMA (unchanged winner).
// grid (18, 2, 4), block 256, dyn smem 69.6KB.
// ---------------------------------------------------------------------------
__global__ void __launch_bounds__(256, 2) oproj_kernel(const float* __restrict__ Wo,
                             float* __restrict__ out) {
    extern __shared__ float sm[];
    float* Wos = sm;                 // [128 o][68]
    float* Pt  = sm + 128 * QS;      // [128 p][68]

    const int p0 = blockIdx.x * 128;
    const int o0 = blockIdx.y * 128;
    const int b2 = blockIdx.z;
    const float* wsr = g_wsr + (size_t)b2 * 512 * NSP;

    const int tid  = threadIdx.x;
    const int w    = tid >> 5;
    const int lane = tid & 31;
    const int gid  = lane >> 2;
    const int tig  = lane & 3;
    const int mr0  = (w >> 1) * 32;
    const int nc0  = (w & 1) * 64;

    float acc[2][8][4];
    #pragma unroll
    for (int mt = 0; mt < 2; mt++)
        #pragma unroll
        for (int nt = 0; nt < 8; nt++)
            #pragma unroll
            for (int j = 0; j < 4; j++) acc[mt][nt][j] = 0.f;

    for (int c0 = 0; c0 < 512; c0 += 64) {
        #pragma unroll
        for (int ps = 0; ps < 8; ps++) {
            int idx = ps * 256 + tid;
            int o = idx >> 4, c4 = idx & 15;
            float4 wv = *(const float4*)&Wo[(size_t)(o0 + o) * 512 + c0 + c4 * 4];
            uint32_t* dst = (uint32_t*)&Wos[o * QS + c4 * 4];
            dst[0] = f2tf(wv.x); dst[1] = f2tf(wv.y);
            dst[2] = f2tf(wv.z); dst[3] = f2tf(wv.w);
        }
        #pragma unroll
        for (int it = 0; it < 32; it++) {
            int idx = it * 256 + tid;
            int p = idx & 127, c = idx >> 7;
            float v = wsr[(size_t)(c0 + c) * NSP + p0 + p];
            *(uint32_t*)&Pt[p * QS + c] = f2tf(v);
        }
        __syncthreads();

        #pragma unroll
        for (int kc = 0; kc < 8; kc++) {
            uint32_t afr[2][4];
            #pragma unroll
            for (int mt = 0; mt < 2; mt++) {
                const uint32_t* ar =
                    (const uint32_t*)&Wos[(mr0 + mt * 16 + gid) * QS + kc * 8 + tig];
                afr[mt][0] = ar[0];
                afr[mt][1] = ar[8 * QS];
                afr[mt][2] = ar[4];
                afr[mt][3] = ar[8 * QS + 4];
            }
            #pragma unroll
            for (int nt = 0; nt < 8; nt++) {
                const uint32_t* br =
                    (const uint32_t*)&Pt[(nc0 + nt * 8 + gid) * QS + kc * 8 + tig];
                uint32_t b0 = br[0], b1 = br[4];
                mma8(acc[0][nt], afr[0], b0, b1);
                mma8(acc[1][nt], afr[1], b0, b1);
            }
        }
        __syncthreads();
    }

    #pragma unroll
    for (int mt = 0; mt < 2; mt++) {
        int orow = o0 + mr0 + mt * 16 + gid;
        #pragma unroll
        for (int nt = 0; nt < 8; nt++) {
            int p = p0 + nc0 + nt * 8 + 2 * tig;
            *(float2*)&out[((size_t)(b2 * 256 + orow)) * NSP + p] =
                make_float2(acc[mt][nt][0], acc[mt][nt][1]);
            *(float2*)&out[((size_t)(b2 * 256 + orow + 8)) * NSP + p] =
                make_float2(acc[mt][nt][2], acc[mt][nt][3]);
        }
    }
}

// ---------------------------------------------------------------------------
extern "C" void kernel_launch(void* const* d_in, const int* in_sizes, int n_in,
                              void* d_out, int out_size) {
    const float* x  = (const float*)d_in[0];
    const float* Wq = (const float*)d_in[1];
    const float* Wk = (const float*)d_in[2];
    const float* Wv = (const float*)d_in[3];
    const float* Wo = (const float*)d_in[4];
    float* out = (float*)d_out;

    const int qkv_smem  = (128 * QS + 64 * QS) * 4;
    const int attn_smem = (2 * 64 * KS2 + 2 * 64 * VS2 + 128 * PS2) * 4; // 55296
    const int oprj_smem = (128 * QS + 128 * QS) * 4;

    cudaFuncSetAttribute(qkv_kernel,
                         cudaFuncAttributeMaxDynamicSharedMemorySize, qkv_smem);
    cudaFuncSetAttribute(attn_kernel,
                         cudaFuncAttributeMaxDynamicSharedMemorySize, attn_smem);
    cudaFuncSetAttribute(oproj_kernel,
                         cudaFuncAttributeMaxDynamicSharedMemorySize, oprj_smem);

    qkv_kernel<<<dim3(NSP / 128, HB, 3), 128, qkv_smem>>>(x, Wq, Wk, Wv);
    attn_kernel<<<dim3(NSP / 128, HB), 256, attn_smem>>>();
    oproj_kernel<<<dim3(NSP / 128, 2, 4), 256, oprj_smem>>>(Wo, out);
}

// round 14
// speedup vs baseline: 2.2755x; 1.1082x over previous
#include <cuda_runtime.h>
#include <cuda_fp16.h>
#include <cstdint>

#define NB   4
#define CIN  256
#define NSP  2304      // 48*48 tokens
#define NH   8
#define HDIM 64
#define HB   32        // NH*NB
// q pre-scale folds softmax scale AND log2(e): exp(s) == exp2(s')
#define QK_SCALE_L2E (0.125f * 1.44269504088896f)

typedef unsigned long long u64;

// Scratch (device globals — no allocations allowed)
// g_q: fp16 [hb][n][d], pre-scaled by 0.125*log2e
// g_k: fp16 [hb][n][d]
// g_v: fp16 [hb][d][n]  (TRANSPOSED for PV .col B-fragments)
// g_wsrh: fp16 scrambled ws [b2][c][p]
__device__ __half g_q   [(size_t)HB * NSP * HDIM];
__device__ __half g_k   [(size_t)HB * NSP * HDIM];
__device__ __half g_v   [(size_t)HB * NSP * HDIM];
__device__ __half g_wsrh[(size_t)4 * 512 * NSP];

// ---- helpers ---------------------------------------------------------------
__device__ __forceinline__ float ex2(float x) {
    float r;
    asm("ex2.approx.f32 %0, %1;" : "=f"(r) : "f"(x));
    return r;
}
// fp16 k16 mma
__device__ __forceinline__ void mma16(float* d, const uint32_t* a,
                                      uint32_t b0, uint32_t b1) {
    asm volatile(
        "mma.sync.aligned.m16n8k16.row.col.f32.f16.f16.f32 "
        "{%0,%1,%2,%3}, {%4,%5,%6,%7}, {%8,%9}, {%0,%1,%2,%3};"
        : "+f"(d[0]), "+f"(d[1]), "+f"(d[2]), "+f"(d[3])
        : "r"(a[0]), "r"(a[1]), "r"(a[2]), "r"(a[3]), "r"(b0), "r"(b1));
}
__device__ __forceinline__ uint32_t s2u(const void* p) {
    return (uint32_t)__cvta_generic_to_shared(p);
}
__device__ __forceinline__ void cp16(uint32_t smem_dst, const void* gsrc) {
    asm volatile("cp.async.cg.shared.global [%0], [%1], 16;"
                 :: "r"(smem_dst), "l"(gsrc));
}
__device__ __forceinline__ uint32_t packh2(float lo, float hi) {
    __half2 h = __floats2half2_rn(lo, hi);
    return *(uint32_t*)&h;
}

#define XS2 36   // row stride (u32 words) for all fp16 smem tiles: 4g+t banks

// ---------------------------------------------------------------------------
// Kernel A: QKV projection via fp16 m16n8k16.
// A = x^T [n][c] fp16 (bank-exact transpose fill); B = W [d][c] fp16.
// Q/K out fp16 [n][d] (q pre-scaled); V out fp16 [d][n] transposed.
// grid (18, 32, 3), block 128, dyn smem 27.6KB -> 4 CTA/SM.
// ---------------------------------------------------------------------------
__global__ void __launch_bounds__(128, 4) qkv_kernel(const float* __restrict__ x,
                           const float* __restrict__ Wq,
                           const float* __restrict__ Wk,
                           const float* __restrict__ Wv) {
    extern __shared__ uint32_t smw[];
    uint32_t* Xth  = smw;                // [128 n][36w] fp16x2 (c-pairs)
    uint32_t* Wsmh = smw + 128 * XS2;    // [64 d][36w]

    const int n0 = blockIdx.x * 128;
    const int hb = blockIdx.y;
    const int m  = blockIdx.z;

    const float* W   = (m == 0 ? Wq : (m == 1 ? Wk : Wv)) + (size_t)(hb >> 2) * HDIM * CIN;
    __half*      out = (m == 0 ? g_q : (m == 1 ? g_k : g_v)) + (size_t)hb * NSP * HDIM;
    const float* xb  = x + (size_t)(hb & 3) * CIN * NSP;
    const float oscale = (m == 0) ? QK_SCALE_L2E : 1.0f;

    const int tid  = threadIdx.x;
    const int w    = tid >> 5;
    const int lane = tid & 31;
    const int gid  = lane >> 2;
    const int tig  = lane & 3;
    const int mr0  = w * 32;

    float acc[2][8][4];
    #pragma unroll
    for (int mt = 0; mt < 2; mt++)
        #pragma unroll
        for (int nt = 0; nt < 8; nt++)
            #pragma unroll
            for (int j = 0; j < 4; j++) acc[mt][nt][j] = 0.f;

    const int l7 = lane & 7, l3 = lane >> 3;

    for (int c0 = 0; c0 < CIN; c0 += 64) {
        // Xth fill: bank-exact transpose. lane l writes row (l&7)+8a, word (l>>3)+4b
        #pragma unroll
        for (int it = 0; it < 32; it++) {
            int a = it & 15;
            int bsel = w + 4 * (it >> 4);
            int n = l7 + 8 * a;
            int wd = l3 + 4 * bsel;
            int c = c0 + 2 * wd;
            float f0 = xb[(size_t)c * NSP + n0 + n];
            float f1 = xb[(size_t)(c + 1) * NSP + n0 + n];
            Xth[n * XS2 + wd] = packh2(f0, f1);
        }
        // Wsmh fill: float4 along c, pack to 2 words
        #pragma unroll
        for (int it = 0; it < 8; it++) {
            int idx = it * 128 + tid;
            int d = idx >> 4, c4 = idx & 15;
            float4 wv = *(const float4*)&W[(size_t)d * CIN + c0 + c4 * 4];
            Wsmh[d * XS2 + c4 * 2]     = packh2(wv.x, wv.y);
            Wsmh[d * XS2 + c4 * 2 + 1] = packh2(wv.z, wv.w);
        }
        __syncthreads();

        #pragma unroll
        for (int kc = 0; kc < 4; kc++) {
            uint32_t afr[2][4];
            #pragma unroll
            for (int mt = 0; mt < 2; mt++) {
                const uint32_t* ar = &Xth[(mr0 + mt * 16 + gid) * XS2 + kc * 8 + tig];
                afr[mt][0] = ar[0];
                afr[mt][1] = ar[8 * XS2];
                afr[mt][2] = ar[4];
                afr[mt][3] = ar[8 * XS2 + 4];
            }
            #pragma unroll
            for (int nt = 0; nt < 8; nt++) {
                const uint32_t* br = &Wsmh[(nt * 8 + gid) * XS2 + kc * 8 + tig];
                uint32_t b0 = br[0], b1 = br[4];
                mma16(acc[0][nt], afr[0], b0, b1);
                mma16(acc[1][nt], afr[1], b0, b1);
            }
        }
        __syncthreads();
    }

    #pragma unroll
    for (int mt = 0; mt < 2; mt++) {
        int r0 = n0 + mr0 + mt * 16 + gid;
        if (m != 2) {
            // Q/K: fp16 [n][d]; d-pair (nt*8+2tig, +1) -> word nt*4+tig
            uint32_t* o0 = (uint32_t*)(out + (size_t)r0 * HDIM);
            uint32_t* o1 = (uint32_t*)(out + (size_t)(r0 + 8) * HDIM);
            #pragma unroll
            for (int nt = 0; nt < 8; nt++) {
                o0[nt * 4 + tig] = packh2(acc[mt][nt][0] * oscale,
                                          acc[mt][nt][1] * oscale);
                o1[nt * 4 + tig] = packh2(acc[mt][nt][2] * oscale,
                                          acc[mt][nt][3] * oscale);
            }
        } else {
            // V: fp16 [d][n] transposed, scalar scatter
            #pragma unroll
            for (int nt = 0; nt < 8; nt++) {
                int d = nt * 8 + 2 * tig;
                out[(size_t)d * NSP + r0]           = __float2half(acc[mt][nt][0]);
                out[(size_t)(d + 1) * NSP + r0]     = __float2half(acc[mt][nt][1]);
                out[(size_t)d * NSP + r0 + 8]       = __float2half(acc[mt][nt][2]);
                out[(size_t)(d + 1) * NSP + r0 + 8] = __float2half(acc[mt][nt][3]);
            }
        }
    }
}

// ---------------------------------------------------------------------------
// Kernel B: fp16 m16n8k16 flash attention (R13 winner; epilogue now fp16 ws).
// grid (18, 32), block 256, dyn smem 54KB -> 2 CTA/SM.
// ---------------------------------------------------------------------------
#define KS2 36
#define VS2 36
#define PS2 36
#define NKT (NSP / 64)

__device__ __forceinline__ void attn_issue_tile(const __half* kg, const __half* vg,
                                                uint32_t* Ks, uint32_t* Vs,
                                                int kt, int buf, int tid) {
    const __half* ksrc = kg + (size_t)kt * 64 * HDIM;
    const __half* vsrc = vg + (size_t)kt * 64;
    uint32_t* kdst = Ks + buf * 64 * KS2;
    uint32_t* vdst = Vs + buf * 64 * VS2;
    #pragma unroll
    for (int it = 0; it < 2; it++) {
        int idx = it * 256 + tid;
        int row = idx >> 3, c4 = idx & 7;
        cp16(s2u(&kdst[row * KS2 + c4 * 4]), ksrc + row * HDIM + c4 * 8);
    }
    #pragma unroll
    for (int it = 0; it < 2; it++) {
        int idx = it * 256 + tid;
        int row = idx >> 3, c4 = idx & 7;
        cp16(s2u(&vdst[row * VS2 + c4 * 4]), vsrc + (size_t)row * NSP + c4 * 8);
    }
    asm volatile("cp.async.commit_group;" ::: "memory");
}

__global__ void __launch_bounds__(256, 2) attn_kernel() {
    extern __shared__ uint32_t smw[];
    uint32_t* Ks = smw;                         // [2][64][36]
    uint32_t* Vs = smw + 2 * 64 * KS2;          // [2][64][36]
    uint32_t* Ps = smw + 2 * 64 * (KS2 + VS2);  // [128][36]

    const int qt = blockIdx.x;
    const int hb = blockIdx.y;
    const int h = hb >> 2, b = hb & 3;

    const __half* qg = g_q + (size_t)hb * NSP * HDIM;
    const __half* kg = g_k + (size_t)hb * NSP * HDIM;
    const __half* vg = g_v + (size_t)hb * NSP * HDIM;

    const int tid  = threadIdx.x;
    const int w    = tid >> 5;
    const int lane = tid & 31;
    const int gid  = lane >> 2;
    const int tig  = lane & 3;
    const int rb   = w * 16;

    attn_issue_tile(kg, vg, Ks, Vs, 0, 0, tid);

    uint32_t qa[4][4];
    {
        const uint32_t* qw0 =
            (const uint32_t*)(qg + (size_t)(qt * 128 + rb + gid) * HDIM);
        const uint32_t* qw1 = qw0 + 8 * (HDIM / 2);
        #pragma unroll
        for (int kc = 0; kc < 4; kc++) {
            qa[kc][0] = qw0[kc * 8 + tig];
            qa[kc][1] = qw1[kc * 8 + tig];
            qa[kc][2] = qw0[kc * 8 + tig + 4];
            qa[kc][3] = qw1[kc * 8 + tig + 4];
        }
    }

    float o[8][4];
    #pragma unroll
    for (int i = 0; i < 8; i++)
        #pragma unroll
        for (int j = 0; j < 4; j++) o[i][j] = 0.f;
    float sum0 = 0.f, sum1 = 0.f;

    for (int kt = 0; kt < NKT; kt++) {
        const int buf = kt & 1;
        asm volatile("cp.async.wait_group 0;" ::: "memory");
        __syncthreads();
        if (kt + 1 < NKT)
            attn_issue_tile(kg, vg, Ks, Vs, kt + 1, buf ^ 1, tid);

        const uint32_t* kb = Ks + buf * 64 * KS2;
        const uint32_t* vb = Vs + buf * 64 * VS2;

        float s[8][4];
        #pragma unroll
        for (int nt = 0; nt < 8; nt++)
            #pragma unroll
            for (int j = 0; j < 4; j++) s[nt][j] = 0.f;

        #pragma unroll
        for (int kc = 0; kc < 4; kc++) {
            #pragma unroll
            for (int nt = 0; nt < 8; nt++) {
                const uint32_t* krow = &kb[(nt * 8 + gid) * KS2 + kc * 8 + tig];
                mma16(s[nt], qa[kc], krow[0], krow[4]);
            }
        }

        #pragma unroll
        for (int nt = 0; nt < 8; nt++) {
            float e0 = ex2(s[nt][0]);
            float e1 = ex2(s[nt][1]);
            float e2 = ex2(s[nt][2]);
            float e3 = ex2(s[nt][3]);
            sum0 += e0 + e1;
            sum1 += e2 + e3;
            Ps[(rb + gid) * PS2 + nt * 4 + tig]     = packh2(e0, e1);
            Ps[(rb + gid + 8) * PS2 + nt * 4 + tig] = packh2(e2, e3);
        }
        __syncwarp();

        #pragma unroll
        for (int kc = 0; kc < 4; kc++) {
            uint32_t pa[4];
            pa[0] = Ps[(rb + gid) * PS2 + kc * 8 + tig];
            pa[1] = Ps[(rb + gid + 8) * PS2 + kc * 8 + tig];
            pa[2] = Ps[(rb + gid) * PS2 + kc * 8 + tig + 4];
            pa[3] = Ps[(rb + gid + 8) * PS2 + kc * 8 + tig + 4];
            #pragma unroll
            for (int nt = 0; nt < 8; nt++) {
                const uint32_t* vrow = &vb[(nt * 8 + gid) * VS2 + kc * 8 + tig];
                mma16(o[nt], pa, vrow[0], vrow[4]);
            }
        }
    }

    sum0 += __shfl_xor_sync(0xffffffffu, sum0, 1);
    sum0 += __shfl_xor_sync(0xffffffffu, sum0, 2);
    sum1 += __shfl_xor_sync(0xffffffffu, sum1, 1);
    sum1 += __shfl_xor_sync(0xffffffffu, sum1, 2);
    const float inv0 = 1.0f / sum0;
    const float inv1 = 1.0f / sum1;

    // ws[h,n,b,d] -> wsrh[(h>>1)*512 + (h&1)*256 + n/9][(n%9)*256 + b*64 + d], fp16
    {
        const int n0 = qt * 128 + rb + gid;
        const int n1 = n0 + 8;
        const size_t ob0 = ((size_t)((h >> 1) * 512 + ((h & 1) << 8) + n0 / 9)) * NSP
                         + (n0 % 9) * 256 + b * 64;
        const size_t ob1 = ((size_t)((h >> 1) * 512 + ((h & 1) << 8) + n1 / 9)) * NSP
                         + (n1 % 9) * 256 + b * 64;
        uint32_t* wp = (uint32_t*)g_wsrh;
        #pragma unroll
        for (int nt = 0; nt < 8; nt++) {
            int d = nt * 8 + 2 * tig;
            wp[(ob0 + d) >> 1] = packh2(o[nt][0] * inv0, o[nt][1] * inv0);
            wp[(ob1 + d) >> 1] = packh2(o[nt][2] * inv1, o[nt][3] * inv1);
        }
    }
}

// ---------------------------------------------------------------------------
// Kernel C: output projection via fp16 m16n8k16.
// A = Wo [o][c] fp16; B = wsrh^T [p][c] fp16 (bank-exact transpose fill).
// grid (18, 2, 4), block 256, dyn smem 36.9KB -> 2 CTA/SM.
// ---------------------------------------------------------------------------
__global__ void __launch_bounds__(256, 2) oproj_kernel(const float* __restrict__ Wo,
                             float* __restrict__ out) {
    extern __shared__ uint32_t smw[];
    uint32_t* Wos = smw;                 // [128 o][36w] fp16x2 (c-pairs)
    uint32_t* Pt  = smw + 128 * XS2;     // [128 p][36w]

    const int p0 = blockIdx.x * 128;
    const int o0 = blockIdx.y * 128;
    const int b2 = blockIdx.z;
    const __half* wsr = g_wsrh + (size_t)b2 * 512 * NSP;

    const int tid  = threadIdx.x;
    const int w    = tid >> 5;
    const int lane = tid & 31;
    const int gid  = lane >> 2;
    const int tig  = lane & 3;
    const int mr0  = (w >> 1) * 32;
    const int nc0  = (w & 1) * 64;
    const int l7 = lane & 7, l3 = lane >> 3;

    float acc[2][8][4];
    #pragma unroll
    for (int mt = 0; mt < 2; mt++)
        #pragma unroll
        for (int nt = 0; nt < 8; nt++)
            #pragma unroll
            for (int j = 0; j < 4; j++) acc[mt][nt][j] = 0.f;

    for (int c0 = 0; c0 < 512; c0 += 64) {
        // Wos: Wo[o][c] float4 along c, pack
        #pragma unroll
        for (int it = 0; it < 8; it++) {
            int idx = it * 256 + tid;
            int o = idx >> 4, c4 = idx & 15;
            float4 wv = *(const float4*)&Wo[(size_t)(o0 + o) * 512 + c0 + c4 * 4];
            Wos[o * XS2 + c4 * 2]     = packh2(wv.x, wv.y);
            Wos[o * XS2 + c4 * 2 + 1] = packh2(wv.z, wv.w);
        }
        // Pt: transpose wsrh[c][p] -> [p][c-pair], bank-exact mapping
        #pragma unroll
        for (int it = 0; it < 16; it++) {
            int p = l7 + 8 * it;
            int wd = l3 + 4 * w;
            int c = c0 + 2 * wd;
            float f0 = __half2float(wsr[(size_t)c * NSP + p0 + p]);
            float f1 = __half2float(wsr[(size_t)(c + 1) * NSP + p0 + p]);
            Pt[p * XS2 + wd] = packh2(f0, f1);
        }
        __syncthreads();

        #pragma unroll
        for (int kc = 0; kc < 4; kc++) {
            uint32_t afr[2][4];
            #pragma unroll
            for (int mt = 0; mt < 2; mt++) {
                const uint32_t* ar = &Wos[(mr0 + mt * 16 + gid) * XS2 + kc * 8 + tig];
                afr[mt][0] = ar[0];
                afr[mt][1] = ar[8 * XS2];
                afr[mt][2] = ar[4];
                afr[mt][3] = ar[8 * XS2 + 4];
            }
            #pragma unroll
            for (int nt = 0; nt < 8; nt++) {
                const uint32_t* br = &Pt[(nc0 + nt * 8 + gid) * XS2 + kc * 8 + tig];
                uint32_t b0 = br[0], b1 = br[4];
                mma16(acc[0][nt], afr[0], b0, b1);
                mma16(acc[1][nt], afr[1], b0, b1);
            }
        }
        __syncthreads();
    }

    #pragma unroll
    for (int mt = 0; mt < 2; mt++) {
        int orow = o0 + mr0 + mt * 16 + gid;
        #pragma unroll
        for (int nt = 0; nt < 8; nt++) {
            int p = p0 + nc0 + nt * 8 + 2 * tig;
            *(float2*)&out[((size_t)(b2 * 256 + orow)) * NSP + p] =
                make_float2(acc[mt][nt][0], acc[mt][nt][1]);
            *(float2*)&out[((size_t)(b2 * 256 + orow + 8)) * NSP + p] =
                make_float2(acc[mt][nt][2], acc[mt][nt][3]);
        }
    }
}

// ---------------------------------------------------------------------------
extern "C" void kernel_launch(void* const* d_in, const int* in_sizes, int n_in,
                              void* d_out, int out_size) {
    const float* x  = (const float*)d_in[0];
    const float* Wq = (const float*)d_in[1];
    const float* Wk = (const float*)d_in[2];
    const float* Wv = (const float*)d_in[3];
    const float* Wo = (const float*)d_in[4];
    float* out = (float*)d_out;

    const int qkv_smem  = (128 * XS2 + 64 * XS2) * 4;                  // 27648
    const int attn_smem = (2 * 64 * KS2 + 2 * 64 * VS2 + 128 * PS2) * 4; // 55296
    const int oprj_smem = (128 * XS2 + 128 * XS2) * 4;                 // 36864

    cudaFuncSetAttribute(qkv_kernel,
                         cudaFuncAttributeMaxDynamicSharedMemorySize, qkv_smem);
    cudaFuncSetAttribute(attn_kernel,
                         cudaFuncAttributeMaxDynamicSharedMemorySize, attn_smem);
    cudaFuncSetAttribute(oproj_kernel,
                         cudaFuncAttributeMaxDynamicSharedMemorySize, oprj_smem);

    qkv_kernel<<<dim3(NSP / 128, HB, 3), 128, qkv_smem>>>(x, Wq, Wk, Wv);
    attn_kernel<<<dim3(NSP / 128, HB), 256, attn_smem>>>();
    oproj_kernel<<<dim3(NSP / 128, 2, 4), 256, oprj_smem>>>(Wo, out);
}

// round 15
// speedup vs baseline: 2.5080x; 1.1022x over previous
#include <cuda_runtime.h>
#include <cuda_fp16.h>
#include <cstdint>

#define NB   4
#define CIN  256
#define NSP  2304      // 48*48 tokens
#define NH   8
#define HDIM 64
#define HB   32        // NH*NB
// q pre-scale folds softmax scale AND log2(e): exp(s) == exp2(s')
#define QK_SCALE_L2E (0.125f * 1.44269504088896f)

typedef unsigned long long u64;

// Scratch (device globals — no allocations allowed)
// g_q: fp16 [hb][n][d], pre-scaled by 0.125*log2e
// g_k: fp16 [hb][n][d]
// g_v: fp16 [hb][d][n]  (TRANSPOSED for PV .col B-fragments)
// g_wsrh: fp16 scrambled ws [b2][c][p]
__device__ __half g_q   [(size_t)HB * NSP * HDIM];
__device__ __half g_k   [(size_t)HB * NSP * HDIM];
__device__ __half g_v   [(size_t)HB * NSP * HDIM];
__device__ __half g_wsrh[(size_t)4 * 512 * NSP];

// ---- helpers ---------------------------------------------------------------
__device__ __forceinline__ float ex2(float x) {
    float r;
    asm("ex2.approx.f32 %0, %1;" : "=f"(r) : "f"(x));
    return r;
}
__device__ __forceinline__ void mma16(float* d, const uint32_t* a,
                                      uint32_t b0, uint32_t b1) {
    asm volatile(
        "mma.sync.aligned.m16n8k16.row.col.f32.f16.f16.f32 "
        "{%0,%1,%2,%3}, {%4,%5,%6,%7}, {%8,%9}, {%0,%1,%2,%3};"
        : "+f"(d[0]), "+f"(d[1]), "+f"(d[2]), "+f"(d[3])
        : "r"(a[0]), "r"(a[1]), "r"(a[2]), "r"(a[3]), "r"(b0), "r"(b1));
}
__device__ __forceinline__ uint32_t s2u(const void* p) {
    return (uint32_t)__cvta_generic_to_shared(p);
}
__device__ __forceinline__ void cp16(uint32_t smem_dst, const void* gsrc) {
    asm volatile("cp.async.cg.shared.global [%0], [%1], 16;"
                 :: "r"(smem_dst), "l"(gsrc));
}
__device__ __forceinline__ uint32_t packh2(float lo, float hi) {
    __half2 h = __floats2half2_rn(lo, hi);
    return *(uint32_t*)&h;
}

// ---------------------------------------------------------------------------
// Kernel A: QKV projection via fp16 m16n8k16, x-tile deduped.
// One CTA = (128-token n-tile, batch b, head-group of 4) -> 12 GEMMs.
// Xth [128 n][132w] fp16 holds ALL 256 c, filled once (bank-exact transpose).
// W streamed through one smem buffer with register-prefetch double buffering.
// grid (18, 4, 2), block 256, dyn smem 101.4KB.
// ---------------------------------------------------------------------------
#define XSW 132   // row stride in u32 words (== 4 mod 32: conflict-free frags)
__global__ void __launch_bounds__(256, 1) qkv_kernel(const float* __restrict__ x,
                           const float* __restrict__ Wq,
                           const float* __restrict__ Wk,
                           const float* __restrict__ Wv) {
    extern __shared__ uint32_t smw[];
    uint32_t* Xth = smw;                 // [128 n][132w] (c-pairs fp16x2)
    uint32_t* Wsm = smw + 128 * XSW;     // [64 d][132w]

    const int n0 = blockIdx.x * 128;
    const int b  = blockIdx.y;
    const int hg = blockIdx.z;           // head group: heads hg*4 .. hg*4+3

    const float* xb = x + (size_t)b * CIN * NSP;

    const int tid  = threadIdx.x;
    const int w    = tid >> 5;
    const int lane = tid & 31;
    const int gid  = lane >> 2;
    const int tig  = lane & 3;
    const int l7   = lane & 7, l3 = lane >> 3;

    // ---- prefetch W for iteration 0 into registers (16 float4/thread)
    float4 wreg[16];
    {
        const float* W = Wq + (size_t)(hg * 4) * HDIM * CIN;   // i=0: m=0, hh=0
        #pragma unroll
        for (int it = 0; it < 16; it++) {
            int idx = it * 256 + tid;
            int d = idx >> 6, c4 = idx & 63;
            wreg[it] = *(const float4*)&W[(size_t)d * CIN + c4 * 4];
        }
    }

    // ---- fill Xth once: transpose x[c][n] -> [n][c-pair] fp16 (bank-exact)
    #pragma unroll
    for (int it = 0; it < 64; it++) {
        int a = it & 15;
        int bsel = w + 8 * (it >> 4);        // 0..31
        int n = l7 + 8 * a;                  // 0..127
        int wd = l3 + 4 * bsel;              // 0..127
        int c = 2 * wd;
        float f0 = xb[(size_t)c * NSP + n0 + n];
        float f1 = xb[(size_t)(c + 1) * NSP + n0 + n];
        Xth[n * XSW + wd] = packh2(f0, f1);
    }

    // ---- 12 GEMM iterations: i -> m = i>>2, h = hg*4 + (i&3)
    for (int i = 0; i < 12; i++) {
        const int m = i >> 2;
        const int h = hg * 4 + (i & 3);
        const int hb = h * 4 + b;
        const float oscale = (m == 0) ? QK_SCALE_L2E : 1.0f;
        __half* out = (m == 0 ? g_q : (m == 1 ? g_k : g_v)) + (size_t)hb * NSP * HDIM;

        // store prefetched W into smem (fp16 packed)
        #pragma unroll
        for (int it = 0; it < 16; it++) {
            int idx = it * 256 + tid;
            int d = idx >> 6, c4 = idx & 63;
            Wsm[d * XSW + c4 * 2]     = packh2(wreg[it].x, wreg[it].y);
            Wsm[d * XSW + c4 * 2 + 1] = packh2(wreg[it].z, wreg[it].w);
        }
        __syncthreads();   // Wsm (and, first iter, Xth) visible

        // prefetch next W while computing
        if (i + 1 < 12) {
            int m2 = (i + 1) >> 2;
            int h2 = hg * 4 + ((i + 1) & 3);
            const float* W = (m2 == 0 ? Wq : (m2 == 1 ? Wk : Wv))
                           + (size_t)h2 * HDIM * CIN;
            #pragma unroll
            for (int it = 0; it < 16; it++) {
                int idx = it * 256 + tid;
                int d = idx >> 6, c4 = idx & 63;
                wreg[it] = *(const float4*)&W[(size_t)d * CIN + c4 * 4];
            }
        }

        // GEMM: 128n x 64d x 256c. Warp w: rows w*16..+16.
        float acc[8][4];
        #pragma unroll
        for (int nt = 0; nt < 8; nt++)
            #pragma unroll
            for (int j = 0; j < 4; j++) acc[nt][j] = 0.f;

        const int r = w * 16 + gid;
        #pragma unroll
        for (int kc = 0; kc < 16; kc++) {
            uint32_t afr[4];
            const uint32_t* ar = &Xth[r * XSW + kc * 8 + tig];
            afr[0] = ar[0];
            afr[1] = ar[8 * XSW];
            afr[2] = ar[4];
            afr[3] = ar[8 * XSW + 4];
            #pragma unroll
            for (int nt = 0; nt < 8; nt++) {
                const uint32_t* br = &Wsm[(nt * 8 + gid) * XSW + kc * 8 + tig];
                mma16(acc[nt], afr, br[0], br[4]);
            }
        }

        // writeout
        int r0 = n0 + w * 16 + gid;
        if (m != 2) {
            uint32_t* o0 = (uint32_t*)(out + (size_t)r0 * HDIM);
            uint32_t* o1 = (uint32_t*)(out + (size_t)(r0 + 8) * HDIM);
            #pragma unroll
            for (int nt = 0; nt < 8; nt++) {
                o0[nt * 4 + tig] = packh2(acc[nt][0] * oscale, acc[nt][1] * oscale);
                o1[nt * 4 + tig] = packh2(acc[nt][2] * oscale, acc[nt][3] * oscale);
            }
        } else {
            #pragma unroll
            for (int nt = 0; nt < 8; nt++) {
                int d = nt * 8 + 2 * tig;
                out[(size_t)d * NSP + r0]           = __float2half(acc[nt][0]);
                out[(size_t)(d + 1) * NSP + r0]     = __float2half(acc[nt][1]);
                out[(size_t)d * NSP + r0 + 8]       = __float2half(acc[nt][2]);
                out[(size_t)(d + 1) * NSP + r0 + 8] = __float2half(acc[nt][3]);
            }
        }
        __syncthreads();   // all reads of Wsm done before next STS
    }
}

// ---------------------------------------------------------------------------
// Kernel B: fp16 m16n8k16 flash attention (R14 winner, unchanged).
// grid (18, 32), block 256, dyn smem 54KB -> 2 CTA/SM.
// ---------------------------------------------------------------------------
#define KS2 36
#define VS2 36
#define PS2 36
#define NKT (NSP / 64)

__device__ __forceinline__ void attn_issue_tile(const __half* kg, const __half* vg,
                                                uint32_t* Ks, uint32_t* Vs,
                                                int kt, int buf, int tid) {
    const __half* ksrc = kg + (size_t)kt * 64 * HDIM;
    const __half* vsrc = vg + (size_t)kt * 64;
    uint32_t* kdst = Ks + buf * 64 * KS2;
    uint32_t* vdst = Vs + buf * 64 * VS2;
    #pragma unroll
    for (int it = 0; it < 2; it++) {
        int idx = it * 256 + tid;
        int row = idx >> 3, c4 = idx & 7;
        cp16(s2u(&kdst[row * KS2 + c4 * 4]), ksrc + row * HDIM + c4 * 8);
    }
    #pragma unroll
    for (int it = 0; it < 2; it++) {
        int idx = it * 256 + tid;
        int row = idx >> 3, c4 = idx & 7;
        cp16(s2u(&vdst[row * VS2 + c4 * 4]), vsrc + (size_t)row * NSP + c4 * 8);
    }
    asm volatile("cp.async.commit_group;" ::: "memory");
}

__global__ void __launch_bounds__(256, 2) attn_kernel() {
    extern __shared__ uint32_t smw[];
    uint32_t* Ks = smw;                         // [2][64][36]
    uint32_t* Vs = smw + 2 * 64 * KS2;          // [2][64][36]
    uint32_t* Ps = smw + 2 * 64 * (KS2 + VS2);  // [128][36]

    const int qt = blockIdx.x;
    const int hb = blockIdx.y;
    const int h = hb >> 2, b = hb & 3;

    const __half* qg = g_q + (size_t)hb * NSP * HDIM;
    const __half* kg = g_k + (size_t)hb * NSP * HDIM;
    const __half* vg = g_v + (size_t)hb * NSP * HDIM;

    const int tid  = threadIdx.x;
    const int w    = tid >> 5;
    const int lane = tid & 31;
    const int gid  = lane >> 2;
    const int tig  = lane & 3;
    const int rb   = w * 16;

    attn_issue_tile(kg, vg, Ks, Vs, 0, 0, tid);

    uint32_t qa[4][4];
    {
        const uint32_t* qw0 =
            (const uint32_t*)(qg + (size_t)(qt * 128 + rb + gid) * HDIM);
        const uint32_t* qw1 = qw0 + 8 * (HDIM / 2);
        #pragma unroll
        for (int kc = 0; kc < 4; kc++) {
            qa[kc][0] = qw0[kc * 8 + tig];
            qa[kc][1] = qw1[kc * 8 + tig];
            qa[kc][2] = qw0[kc * 8 + tig + 4];
            qa[kc][3] = qw1[kc * 8 + tig + 4];
        }
    }

    float o[8][4];
    #pragma unroll
    for (int i = 0; i < 8; i++)
        #pragma unroll
        for (int j = 0; j < 4; j++) o[i][j] = 0.f;
    float sum0 = 0.f, sum1 = 0.f;

    for (int kt = 0; kt < NKT; kt++) {
        const int buf = kt & 1;
        asm volatile("cp.async.wait_group 0;" ::: "memory");
        __syncthreads();
        if (kt + 1 < NKT)
            attn_issue_tile(kg, vg, Ks, Vs, kt + 1, buf ^ 1, tid);

        const uint32_t* kb = Ks + buf * 64 * KS2;
        const uint32_t* vb = Vs + buf * 64 * VS2;

        float s[8][4];
        #pragma unroll
        for (int nt = 0; nt < 8; nt++)
            #pragma unroll
            for (int j = 0; j < 4; j++) s[nt][j] = 0.f;

        #pragma unroll
        for (int kc = 0; kc < 4; kc++) {
            #pragma unroll
            for (int nt = 0; nt < 8; nt++) {
                const uint32_t* krow = &kb[(nt * 8 + gid) * KS2 + kc * 8 + tig];
                mma16(s[nt], qa[kc], krow[0], krow[4]);
            }
        }

        #pragma unroll
        for (int nt = 0; nt < 8; nt++) {
            float e0 = ex2(s[nt][0]);
            float e1 = ex2(s[nt][1]);
            float e2 = ex2(s[nt][2]);
            float e3 = ex2(s[nt][3]);
            sum0 += e0 + e1;
            sum1 += e2 + e3;
            Ps[(rb + gid) * PS2 + nt * 4 + tig]     = packh2(e0, e1);
            Ps[(rb + gid + 8) * PS2 + nt * 4 + tig] = packh2(e2, e3);
        }
        __syncwarp();

        #pragma unroll
        for (int kc = 0; kc < 4; kc++) {
            uint32_t pa[4];
            pa[0] = Ps[(rb + gid) * PS2 + kc * 8 + tig];
            pa[1] = Ps[(rb + gid + 8) * PS2 + kc * 8 + tig];
            pa[2] = Ps[(rb + gid) * PS2 + kc * 8 + tig + 4];
            pa[3] = Ps[(rb + gid + 8) * PS2 + kc * 8 + tig + 4];
            #pragma unroll
            for (int nt = 0; nt < 8; nt++) {
                const uint32_t* vrow = &vb[(nt * 8 + gid) * VS2 + kc * 8 + tig];
                mma16(o[nt], pa, vrow[0], vrow[4]);
            }
        }
    }

    sum0 += __shfl_xor_sync(0xffffffffu, sum0, 1);
    sum0 += __shfl_xor_sync(0xffffffffu, sum0, 2);
    sum1 += __shfl_xor_sync(0xffffffffu, sum1, 1);
    sum1 += __shfl_xor_sync(0xffffffffu, sum1, 2);
    const float inv0 = 1.0f / sum0;
    const float inv1 = 1.0f / sum1;

    // ws[h,n,b,d] -> wsrh[(h>>1)*512 + (h&1)*256 + n/9][(n%9)*256 + b*64 + d], fp16
    {
        const int n0 = qt * 128 + rb + gid;
        const int n1 = n0 + 8;
        const size_t ob0 = ((size_t)((h >> 1) * 512 + ((h & 1) << 8) + n0 / 9)) * NSP
                         + (n0 % 9) * 256 + b * 64;
        const size_t ob1 = ((size_t)((h >> 1) * 512 + ((h & 1) << 8) + n1 / 9)) * NSP
                         + (n1 % 9) * 256 + b * 64;
        uint32_t* wp = (uint32_t*)g_wsrh;
        #pragma unroll
        for (int nt = 0; nt < 8; nt++) {
            int d = nt * 8 + 2 * tig;
            wp[(ob0 + d) >> 1] = packh2(o[nt][0] * inv0, o[nt][1] * inv0);
            wp[(ob1 + d) >> 1] = packh2(o[nt][2] * inv1, o[nt][3] * inv1);
        }
    }
}

// ---------------------------------------------------------------------------
// Kernel C: output projection via fp16 m16n8k16 (R14 winner, unchanged).
// grid (18, 2, 4), block 256, dyn smem 36.9KB -> 2 CTA/SM.
// ---------------------------------------------------------------------------
#define XS2 36
__global__ void __launch_bounds__(256, 2) oproj_kernel(const float* __restrict__ Wo,
                             float* __restrict__ out) {
    extern __shared__ uint32_t smw[];
    uint32_t* Wos = smw;                 // [128 o][36w]
    uint32_t* Pt  = smw + 128 * XS2;     // [128 p][36w]

    const int p0 = blockIdx.x * 128;
    const int o0 = blockIdx.y * 128;
    const int b2 = blockIdx.z;
    const __half* wsr = g_wsrh + (size_t)b2 * 512 * NSP;

    const int tid  = threadIdx.x;
    const int w    = tid >> 5;
    const int lane = tid & 31;
    const int gid  = lane >> 2;
    const int tig  = lane & 3;
    const int mr0  = (w >> 1) * 32;
    const int nc0  = (w & 1) * 64;
    const int l7 = lane & 7, l3 = lane >> 3;

    float acc[2][8][4];
    #pragma unroll
    for (int mt = 0; mt < 2; mt++)
        #pragma unroll
        for (int nt = 0; nt < 8; nt++)
            #pragma unroll
            for (int j = 0; j < 4; j++) acc[mt][nt][j] = 0.f;

    for (int c0 = 0; c0 < 512; c0 += 64) {
        #pragma unroll
        for (int it = 0; it < 8; it++) {
            int idx = it * 256 + tid;
            int o = idx >> 4, c4 = idx & 15;
            float4 wv = *(const float4*)&Wo[(size_t)(o0 + o) * 512 + c0 + c4 * 4];
            Wos[o * XS2 + c4 * 2]     = packh2(wv.x, wv.y);
            Wos[o * XS2 + c4 * 2 + 1] = packh2(wv.z, wv.w);
        }
        #pragma unroll
        for (int it = 0; it < 16; it++) {
            int p = l7 + 8 * it;
            int wd = l3 + 4 * w;
            int c = c0 + 2 * wd;
            float f0 = __half2float(wsr[(size_t)c * NSP + p0 + p]);
            float f1 = __half2float(wsr[(size_t)(c + 1) * NSP + p0 + p]);
            Pt[p * XS2 + wd] = packh2(f0, f1);
        }
        __syncthreads();

        #pragma unroll
        for (int kc = 0; kc < 4; kc++) {
            uint32_t afr[2][4];
            #pragma unroll
            for (int mt = 0; mt < 2; mt++) {
                const uint32_t* ar = &Wos[(mr0 + mt * 16 + gid) * XS2 + kc * 8 + tig];
                afr[mt][0] = ar[0];
                afr[mt][1] = ar[8 * XS2];
                afr[mt][2] = ar[4];
                afr[mt][3] = ar[8 * XS2 + 4];
            }
            #pragma unroll
            for (int nt = 0; nt < 8; nt++) {
                const uint32_t* br = &Pt[(nc0 + nt * 8 + gid) * XS2 + kc * 8 + tig];
                uint32_t b0 = br[0], b1 = br[4];
                mma16(acc[0][nt], afr[0], b0, b1);
                mma16(acc[1][nt], afr[1], b0, b1);
            }
        }
        __syncthreads();
    }

    #pragma unroll
    for (int mt = 0; mt < 2; mt++) {
        int orow = o0 + mr0 + mt * 16 + gid;
        #pragma unroll
        for (int nt = 0; nt < 8; nt++) {
            int p = p0 + nc0 + nt * 8 + 2 * tig;
            *(float2*)&out[((size_t)(b2 * 256 + orow)) * NSP + p] =
                make_float2(acc[mt][nt][0], acc[mt][nt][1]);
            *(float2*)&out[((size_t)(b2 * 256 + orow + 8)) * NSP + p] =
                make_float2(acc[mt][nt][2], acc[mt][nt][3]);
        }
    }
}

// ---------------------------------------------------------------------------
extern "C" void kernel_launch(void* const* d_in, const int* in_sizes, int n_in,
                              void* d_out, int out_size) {
    const float* x  = (const float*)d_in[0];
    const float* Wq = (const float*)d_in[1];
    const float* Wk = (const float*)d_in[2];
    const float* Wv = (const float*)d_in[3];
    const float* Wo = (const float*)d_in[4];
    float* out = (float*)d_out;

    const int qkv_smem  = (128 * XSW + 64 * XSW) * 4;                  // 101376
    const int attn_smem = (2 * 64 * KS2 + 2 * 64 * VS2 + 128 * PS2) * 4; // 55296
    const int oprj_smem = (128 * XS2 + 128 * XS2) * 4;                 // 36864

    cudaFuncSetAttribute(qkv_kernel,
                         cudaFuncAttributeMaxDynamicSharedMemorySize, qkv_smem);
    cudaFuncSetAttribute(attn_kernel,
                         cudaFuncAttributeMaxDynamicSharedMemorySize, attn_smem);
    cudaFuncSetAttribute(oproj_kernel,
                         cudaFuncAttributeMaxDynamicSharedMemorySize, oprj_smem);

    qkv_kernel<<<dim3(NSP / 128, NB, 2), 256, qkv_smem>>>(x, Wq, Wk, Wv);
    attn_kernel<<<dim3(NSP / 128, HB), 256, attn_smem>>>();
    oproj_kernel<<<dim3(NSP / 128, 2, 4), 256, oprj_smem>>>(Wo, out);
}

// round 16
// speedup vs baseline: 2.6968x; 1.0753x over previous
#include <cuda_runtime.h>
#include <cuda_fp16.h>
#include <cstdint>

#define NB   4
#define CIN  256
#define NSP  2304      // 48*48 tokens
#define NH   8
#define HDIM 64
#define HB   32        // NH*NB
// q pre-scale folds softmax scale AND log2(e): exp(s) == exp2(s')
#define QK_SCALE_L2E (0.125f * 1.44269504088896f)

typedef unsigned long long u64;

// Scratch (device globals — no allocations allowed)
__device__ __half g_q   [(size_t)HB * NSP * HDIM];
__device__ __half g_k   [(size_t)HB * NSP * HDIM];
__device__ __half g_v   [(size_t)HB * NSP * HDIM];   // [hb][d][n] transposed
__device__ __half g_wsrh[(size_t)4 * 512 * NSP];     // fp16 scrambled ws

// ---- helpers ---------------------------------------------------------------
__device__ __forceinline__ float ex2(float x) {
    float r;
    asm("ex2.approx.f32 %0, %1;" : "=f"(r) : "f"(x));
    return r;
}
__device__ __forceinline__ void mma16(float* d, const uint32_t* a,
                                      uint32_t b0, uint32_t b1) {
    asm volatile(
        "mma.sync.aligned.m16n8k16.row.col.f32.f16.f16.f32 "
        "{%0,%1,%2,%3}, {%4,%5,%6,%7}, {%8,%9}, {%0,%1,%2,%3};"
        : "+f"(d[0]), "+f"(d[1]), "+f"(d[2]), "+f"(d[3])
        : "r"(a[0]), "r"(a[1]), "r"(a[2]), "r"(a[3]), "r"(b0), "r"(b1));
}
// 4x 8x8 b16 matrices in one instruction
__device__ __forceinline__ void ldsm4(uint32_t* r, uint32_t addr) {
    asm volatile(
        "ldmatrix.sync.aligned.m8n8.x4.shared.b16 {%0,%1,%2,%3}, [%4];"
        : "=r"(r[0]), "=r"(r[1]), "=r"(r[2]), "=r"(r[3]) : "r"(addr));
}
__device__ __forceinline__ uint32_t s2u(const void* p) {
    return (uint32_t)__cvta_generic_to_shared(p);
}
__device__ __forceinline__ void cp16(uint32_t smem_dst, const void* gsrc) {
    asm volatile("cp.async.cg.shared.global [%0], [%1], 16;"
                 :: "r"(smem_dst), "l"(gsrc));
}
__device__ __forceinline__ uint32_t packh2(float lo, float hi) {
    __half2 h = __floats2half2_rn(lo, hi);
    return *(uint32_t*)&h;
}

// ldmatrix per-lane offsets (words), stride S:
//  B-type (4 mats = rows blk..+7/+8..+15 x words 0/+4): ((m>>1)*8+r)*S + (m&1)*4
//  A-type (a0..a3 of m16n8k16):                        ((m&1)*8+r)*S + (m>>1)*4
#define LDSM_B_OFF(S, mm, rr) (((((mm) >> 1) * 8 + (rr)) * (S) + ((mm) & 1) * 4) * 4)
#define LDSM_A_OFF(S, mm, rr) (((((mm) & 1) * 8 + (rr)) * (S) + ((mm) >> 1) * 4) * 4)

// ---------------------------------------------------------------------------
// Kernel A: QKV projection via fp16 m16n8k16 + ldmatrix, x-tile deduped.
// grid (18, 4, 2), block 256, dyn smem 101.4KB.
// ---------------------------------------------------------------------------
#define XSW 132
__global__ void __launch_bounds__(256, 1) qkv_kernel(const float* __restrict__ x,
                           const float* __restrict__ Wq,
                           const float* __restrict__ Wk,
                           const float* __restrict__ Wv) {
    extern __shared__ uint32_t smw[];
    uint32_t* Xth = smw;                 // [128 n][132w] (c-pairs fp16x2)
    uint32_t* Wsm = smw + 128 * XSW;     // [64 d][132w]

    const int n0 = blockIdx.x * 128;
    const int b  = blockIdx.y;
    const int hg = blockIdx.z;

    const float* xb = x + (size_t)b * CIN * NSP;

    const int tid  = threadIdx.x;
    const int w    = tid >> 5;
    const int lane = tid & 31;
    const int tig  = lane & 3;
    const int gid  = lane >> 2;
    const int l7   = lane & 7, l3 = lane >> 3;
    const int mm   = lane >> 3, rr = lane & 7;

    const uint32_t Xu = s2u(Xth), Wu = s2u(Wsm);
    const uint32_t aoffX = LDSM_A_OFF(XSW, mm, rr);
    const uint32_t boffX = LDSM_B_OFF(XSW, mm, rr);

    // prefetch W for iteration 0
    float4 wreg[16];
    {
        const float* W = Wq + (size_t)(hg * 4) * HDIM * CIN;
        #pragma unroll
        for (int it = 0; it < 16; it++) {
            int idx = it * 256 + tid;
            int d = idx >> 6, c4 = idx & 63;
            wreg[it] = *(const float4*)&W[(size_t)d * CIN + c4 * 4];
        }
    }

    // fill Xth once: transpose x[c][n] -> [n][c-pair] fp16 (bank-exact)
    #pragma unroll
    for (int it = 0; it < 64; it++) {
        int a = it & 15;
        int bsel = w + 8 * (it >> 4);
        int n = l7 + 8 * a;
        int wd = l3 + 4 * bsel;
        int c = 2 * wd;
        float f0 = xb[(size_t)c * NSP + n0 + n];
        float f1 = xb[(size_t)(c + 1) * NSP + n0 + n];
        Xth[n * XSW + wd] = packh2(f0, f1);
    }

    for (int i = 0; i < 12; i++) {
        const int m = i >> 2;
        const int h = hg * 4 + (i & 3);
        const int hb = h * 4 + b;
        const float oscale = (m == 0) ? QK_SCALE_L2E : 1.0f;
        __half* out = (m == 0 ? g_q : (m == 1 ? g_k : g_v)) + (size_t)hb * NSP * HDIM;

        #pragma unroll
        for (int it = 0; it < 16; it++) {
            int idx = it * 256 + tid;
            int d = idx >> 6, c4 = idx & 63;
            Wsm[d * XSW + c4 * 2]     = packh2(wreg[it].x, wreg[it].y);
            Wsm[d * XSW + c4 * 2 + 1] = packh2(wreg[it].z, wreg[it].w);
        }
        __syncthreads();

        if (i + 1 < 12) {
            int m2 = (i + 1) >> 2;
            int h2 = hg * 4 + ((i + 1) & 3);
            const float* W = (m2 == 0 ? Wq : (m2 == 1 ? Wk : Wv))
                           + (size_t)h2 * HDIM * CIN;
            #pragma unroll
            for (int it = 0; it < 16; it++) {
                int idx = it * 256 + tid;
                int d = idx >> 6, c4 = idx & 63;
                wreg[it] = *(const float4*)&W[(size_t)d * CIN + c4 * 4];
            }
        }

        float acc[8][4];
        #pragma unroll
        for (int nt = 0; nt < 8; nt++)
            #pragma unroll
            for (int j = 0; j < 4; j++) acc[nt][j] = 0.f;

        #pragma unroll
        for (int kc = 0; kc < 16; kc++) {
            uint32_t afr[4];
            ldsm4(afr, Xu + ((w * 16) * XSW + kc * 8) * 4 + aoffX);
            #pragma unroll
            for (int nt2 = 0; nt2 < 4; nt2++) {
                uint32_t b4[4];
                ldsm4(b4, Wu + (nt2 * 16 * XSW + kc * 8) * 4 + boffX);
                mma16(acc[2 * nt2],     afr, b4[0], b4[1]);
                mma16(acc[2 * nt2 + 1], afr, b4[2], b4[3]);
            }
        }

        int r0 = n0 + w * 16 + gid;
        if (m != 2) {
            uint32_t* o0 = (uint32_t*)(out + (size_t)r0 * HDIM);
            uint32_t* o1 = (uint32_t*)(out + (size_t)(r0 + 8) * HDIM);
            #pragma unroll
            for (int nt = 0; nt < 8; nt++) {
                o0[nt * 4 + tig] = packh2(acc[nt][0] * oscale, acc[nt][1] * oscale);
                o1[nt * 4 + tig] = packh2(acc[nt][2] * oscale, acc[nt][3] * oscale);
            }
        } else {
            #pragma unroll
            for (int nt = 0; nt < 8; nt++) {
                int d = nt * 8 + 2 * tig;
                out[(size_t)d * NSP + r0]           = __float2half(acc[nt][0]);
                out[(size_t)(d + 1) * NSP + r0]     = __float2half(acc[nt][1]);
                out[(size_t)d * NSP + r0 + 8]       = __float2half(acc[nt][2]);
                out[(size_t)(d + 1) * NSP + r0 + 8] = __float2half(acc[nt][3]);
            }
        }
        __syncthreads();
    }
}

// ---------------------------------------------------------------------------
// Kernel B: fp16 m16n8k16 flash attention + ldmatrix fragments.
// grid (18, 32), block 256, dyn smem 54KB -> 2 CTA/SM.
// ---------------------------------------------------------------------------
#define KS2 36
#define VS2 36
#define PS2 36
#define NKT (NSP / 64)

__device__ __forceinline__ void attn_issue_tile(const __half* kg, const __half* vg,
                                                uint32_t* Ks, uint32_t* Vs,
                                                int kt, int buf, int tid) {
    const __half* ksrc = kg + (size_t)kt * 64 * HDIM;
    const __half* vsrc = vg + (size_t)kt * 64;
    uint32_t* kdst = Ks + buf * 64 * KS2;
    uint32_t* vdst = Vs + buf * 64 * VS2;
    #pragma unroll
    for (int it = 0; it < 2; it++) {
        int idx = it * 256 + tid;
        int row = idx >> 3, c4 = idx & 7;
        cp16(s2u(&kdst[row * KS2 + c4 * 4]), ksrc + row * HDIM + c4 * 8);
    }
    #pragma unroll
    for (int it = 0; it < 2; it++) {
        int idx = it * 256 + tid;
        int row = idx >> 3, c4 = idx & 7;
        cp16(s2u(&vdst[row * VS2 + c4 * 4]), vsrc + (size_t)row * NSP + c4 * 8);
    }
    asm volatile("cp.async.commit_group;" ::: "memory");
}

__global__ void __launch_bounds__(256, 2) attn_kernel() {
    extern __shared__ uint32_t smw[];
    uint32_t* Ks = smw;                         // [2][64][36]
    uint32_t* Vs = smw + 2 * 64 * KS2;          // [2][64][36]
    uint32_t* Ps = smw + 2 * 64 * (KS2 + VS2);  // [128][36]

    const int qt = blockIdx.x;
    const int hb = blockIdx.y;
    const int h = hb >> 2, b = hb & 3;

    const __half* qg = g_q + (size_t)hb * NSP * HDIM;
    const __half* kg = g_k + (size_t)hb * NSP * HDIM;
    const __half* vg = g_v + (size_t)hb * NSP * HDIM;

    const int tid  = threadIdx.x;
    const int w    = tid >> 5;
    const int lane = tid & 31;
    const int gid  = lane >> 2;
    const int tig  = lane & 3;
    const int rb   = w * 16;
    const int mm   = lane >> 3, rr = lane & 7;

    const uint32_t Ks_u = s2u(Ks), Vs_u = s2u(Vs), Ps_u = s2u(Ps);
    const uint32_t boffB = LDSM_B_OFF(36, mm, rr);   // K & V (stride 36)
    const uint32_t aoffP = LDSM_A_OFF(36, mm, rr);   // P A-fragments

    attn_issue_tile(kg, vg, Ks, Vs, 0, 0, tid);

    uint32_t qa[4][4];
    {
        const uint32_t* qw0 =
            (const uint32_t*)(qg + (size_t)(qt * 128 + rb + gid) * HDIM);
        const uint32_t* qw1 = qw0 + 8 * (HDIM / 2);
        #pragma unroll
        for (int kc = 0; kc < 4; kc++) {
            qa[kc][0] = qw0[kc * 8 + tig];
            qa[kc][1] = qw1[kc * 8 + tig];
            qa[kc][2] = qw0[kc * 8 + tig + 4];
            qa[kc][3] = qw1[kc * 8 + tig + 4];
        }
    }

    float o[8][4];
    #pragma unroll
    for (int i = 0; i < 8; i++)
        #pragma unroll
        for (int j = 0; j < 4; j++) o[i][j] = 0.f;
    float sum0 = 0.f, sum1 = 0.f;

    for (int kt = 0; kt < NKT; kt++) {
        const int buf = kt & 1;
        asm volatile("cp.async.wait_group 0;" ::: "memory");
        __syncthreads();
        if (kt + 1 < NKT)
            attn_issue_tile(kg, vg, Ks, Vs, kt + 1, buf ^ 1, tid);

        const uint32_t kb_u = Ks_u + buf * 64 * KS2 * 4;
        const uint32_t vb_u = Vs_u + buf * 64 * VS2 * 4;

        // ---- S = Q @ K^T
        float s[8][4];
        #pragma unroll
        for (int nt = 0; nt < 8; nt++)
            #pragma unroll
            for (int j = 0; j < 4; j++) s[nt][j] = 0.f;

        #pragma unroll
        for (int kc = 0; kc < 4; kc++) {
            #pragma unroll
            for (int nt2 = 0; nt2 < 4; nt2++) {
                uint32_t b4[4];
                ldsm4(b4, kb_u + (nt2 * 16 * KS2 + kc * 8) * 4 + boffB);
                mma16(s[2 * nt2],     qa[kc], b4[0], b4[1]);
                mma16(s[2 * nt2 + 1], qa[kc], b4[2], b4[3]);
            }
        }

        // ---- softmax: ex2 (scale pre-folded), f32 sums, fp16x2 P store
        #pragma unroll
        for (int nt = 0; nt < 8; nt++) {
            float e0 = ex2(s[nt][0]);
            float e1 = ex2(s[nt][1]);
            float e2 = ex2(s[nt][2]);
            float e3 = ex2(s[nt][3]);
            sum0 += e0 + e1;
            sum1 += e2 + e3;
            Ps[(rb + gid) * PS2 + nt * 4 + tig]     = packh2(e0, e1);
            Ps[(rb + gid + 8) * PS2 + nt * 4 + tig] = packh2(e2, e3);
        }
        __syncwarp();

        // ---- O += P @ V
        #pragma unroll
        for (int kc = 0; kc < 4; kc++) {
            uint32_t pa[4];
            ldsm4(pa, Ps_u + (rb * PS2 + kc * 8) * 4 + aoffP);
            #pragma unroll
            for (int nt2 = 0; nt2 < 4; nt2++) {
                uint32_t v4[4];
                ldsm4(v4, vb_u + (nt2 * 16 * VS2 + kc * 8) * 4 + boffB);
                mma16(o[2 * nt2],     pa, v4[0], v4[1]);
                mma16(o[2 * nt2 + 1], pa, v4[2], v4[3]);
            }
        }
    }

    sum0 += __shfl_xor_sync(0xffffffffu, sum0, 1);
    sum0 += __shfl_xor_sync(0xffffffffu, sum0, 2);
    sum1 += __shfl_xor_sync(0xffffffffu, sum1, 1);
    sum1 += __shfl_xor_sync(0xffffffffu, sum1, 2);
    const float inv0 = 1.0f / sum0;
    const float inv1 = 1.0f / sum1;

    {
        const int n0 = qt * 128 + rb + gid;
        const int n1 = n0 + 8;
        const size_t ob0 = ((size_t)((h >> 1) * 512 + ((h & 1) << 8) + n0 / 9)) * NSP
                         + (n0 % 9) * 256 + b * 64;
        const size_t ob1 = ((size_t)((h >> 1) * 512 + ((h & 1) << 8) + n1 / 9)) * NSP
                         + (n1 % 9) * 256 + b * 64;
        uint32_t* wp = (uint32_t*)g_wsrh;
        #pragma unroll
        for (int nt = 0; nt < 8; nt++) {
            int d = nt * 8 + 2 * tig;
            wp[(ob0 + d) >> 1] = packh2(o[nt][0] * inv0, o[nt][1] * inv0);
            wp[(ob1 + d) >> 1] = packh2(o[nt][2] * inv1, o[nt][3] * inv1);
        }
    }
}

// ---------------------------------------------------------------------------
// Kernel C: output projection via fp16 m16n8k16 + ldmatrix.
// grid (18, 2, 4), block 256, dyn smem 36.9KB -> 2 CTA/SM.
// ---------------------------------------------------------------------------
#define XS2 36
__global__ void __launch_bounds__(256, 2) oproj_kernel(const float* __restrict__ Wo,
                             float* __restrict__ out) {
    extern __shared__ uint32_t smw[];
    uint32_t* Wos = smw;                 // [128 o][36w]
    uint32_t* Pt  = smw + 128 * XS2;     // [128 p][36w]

    const int p0 = blockIdx.x * 128;
    const int o0 = blockIdx.y * 128;
    const int b2 = blockIdx.z;
    const __half* wsr = g_wsrh + (size_t)b2 * 512 * NSP;

    const int tid  = threadIdx.x;
    const int w    = tid >> 5;
    const int lane = tid & 31;
    const int gid  = lane >> 2;
    const int tig  = lane & 3;
    const int mr0  = (w >> 1) * 32;
    const int nc0  = (w & 1) * 64;
    const int l7 = lane & 7, l3 = lane >> 3;
    const int mm = lane >> 3, rr = lane & 7;

    const uint32_t Wu = s2u(Wos), Pu = s2u(Pt);
    const uint32_t aoffO = LDSM_A_OFF(XS2, mm, rr);
    const uint32_t boffO = LDSM_B_OFF(XS2, mm, rr);

    float acc[2][8][4];
    #pragma unroll
    for (int mt = 0; mt < 2; mt++)
        #pragma unroll
        for (int nt = 0; nt < 8; nt++)
            #pragma unroll
            for (int j = 0; j < 4; j++) acc[mt][nt][j] = 0.f;

    for (int c0 = 0; c0 < 512; c0 += 64) {
        #pragma unroll
        for (int it = 0; it < 8; it++) {
            int idx = it * 256 + tid;
            int o = idx >> 4, c4 = idx & 15;
            float4 wv = *(const float4*)&Wo[(size_t)(o0 + o) * 512 + c0 + c4 * 4];
            Wos[o * XS2 + c4 * 2]     = packh2(wv.x, wv.y);
            Wos[o * XS2 + c4 * 2 + 1] = packh2(wv.z, wv.w);
        }
        #pragma unroll
        for (int it = 0; it < 16; it++) {
            int p = l7 + 8 * it;
            int wd = l3 + 4 * w;
            int c = c0 + 2 * wd;
            float f0 = __half2float(wsr[(size_t)c * NSP + p0 + p]);
            float f1 = __half2float(wsr[(size_t)(c + 1) * NSP + p0 + p]);
            Pt[p * XS2 + wd] = packh2(f0, f1);
        }
        __syncthreads();

        #pragma unroll
        for (int kc = 0; kc < 4; kc++) {
            uint32_t afr0[4], afr1[4];
            ldsm4(afr0, Wu + (mr0 * XS2 + kc * 8) * 4 + aoffO);
            ldsm4(afr1, Wu + ((mr0 + 16) * XS2 + kc * 8) * 4 + aoffO);
            #pragma unroll
            for (int nt2 = 0; nt2 < 4; nt2++) {
                uint32_t b4[4];
                ldsm4(b4, Pu + ((nc0 + nt2 * 16) * XS2 + kc * 8) * 4 + boffO);
                mma16(acc[0][2 * nt2],     afr0, b4[0], b4[1]);
                mma16(acc[0][2 * nt2 + 1], afr0, b4[2], b4[3]);
                mma16(acc[1][2 * nt2],     afr1, b4[0], b4[1]);
                mma16(acc[1][2 * nt2 + 1], afr1, b4[2], b4[3]);
            }
        }
        __syncthreads();
    }

    #pragma unroll
    for (int mt = 0; mt < 2; mt++) {
        int orow = o0 + mr0 + mt * 16 + gid;
        #pragma unroll
        for (int nt = 0; nt < 8; nt++) {
            int p = p0 + nc0 + nt * 8 + 2 * tig;
            *(float2*)&out[((size_t)(b2 * 256 + orow)) * NSP + p] =
                make_float2(acc[mt][nt][0], acc[mt][nt][1]);
            *(float2*)&out[((size_t)(b2 * 256 + orow + 8)) * NSP + p] =
                make_float2(acc[mt][nt][2], acc[mt][nt][3]);
        }
    }
}

// ---------------------------------------------------------------------------
extern "C" void kernel_launch(void* const* d_in, const int* in_sizes, int n_in,
                              void* d_out, int out_size) {
    const float* x  = (const float*)d_in[0];
    const float* Wq = (const float*)d_in[1];
    const float* Wk = (const float*)d_in[2];
    const float* Wv = (const float*)d_in[3];
    const float* Wo = (const float*)d_in[4];
    float* out = (float*)d_out;

    const int qkv_smem  = (128 * XSW + 64 * XSW) * 4;                  // 101376
    const int attn_smem = (2 * 64 * KS2 + 2 * 64 * VS2 + 128 * PS2) * 4; // 55296
    const int oprj_smem = (128 * XS2 + 128 * XS2) * 4;                 // 36864

    cudaFuncSetAttribute(qkv_kernel,
                         cudaFuncAttributeMaxDynamicSharedMemorySize, qkv_smem);
    cudaFuncSetAttribute(attn_kernel,
                         cudaFuncAttributeMaxDynamicSharedMemorySize, attn_smem);
    cudaFuncSetAttribute(oproj_kernel,
                         cudaFuncAttributeMaxDynamicSharedMemorySize, oprj_smem);

    qkv_kernel<<<dim3(NSP / 128, NB, 2), 256, qkv_smem>>>(x, Wq, Wk, Wv);
    attn_kernel<<<dim3(NSP / 128, HB), 256, attn_smem>>>();
    oproj_kernel<<<dim3(NSP / 128, 2, 4), 256, oprj_smem>>>(Wo, out);
}